// round 13
// baseline (speedup 1.0000x reference)
#include <cuda_runtime.h>
#include <cstdint>

#define NQ   32
#define KCB  1024
#define CD   8
#define DD   1024
#define TT   4096
#define BB   8
#define NCOL (BB * TT)

#define QOUT_ELEMS (BB * DD * TT)
#define IDX_ELEMS  (NQ * BB * TT)
#define FULL_OUT   (QOUT_ELEMS + IDX_ELEMS + BB)

typedef unsigned long long u64t;

__device__ __forceinline__ u64t pk2(float a, float b) {
    u64t r; asm("mov.b64 %0,{%1,%2};" : "=l"(r) : "f"(a), "f"(b)); return r;
}
__device__ __forceinline__ float2 upk2(u64t v) {
    float2 r; asm("mov.b64 {%0,%1},%2;" : "=f"(r.x), "=f"(r.y) : "l"(v)); return r;
}
__device__ __forceinline__ void fma2(u64t& d, u64t a, u64t b) {
    asm("fma.rn.f32x2 %0,%1,%2,%0;" : "+l"(d) : "l"(a), "l"(b));
}
__device__ __forceinline__ u64t mul2(u64t a, u64t b) {
    u64t r; asm("mul.rn.f32x2 %0,%1,%2;" : "=l"(r) : "l"(a), "l"(b)); return r;
}

// scratch (device globals; zero-alloc rule)
__device__ float g_ZE0[256 * NCOL];      // [mc][col]
__device__ float g_ZQ [256 * NCOL];      // [mc][col], masked zq
__device__ float g_G  [256 * 256];
__device__ float g_WinTT[DD * 256];      // [k][m]  A^T for gemmZE
__device__ float g_WoT2 [256 * DD];      // [mc][d] A^T for gemmQ + kG operand
__device__ float g_cbn[NQ * KCB * CD];
__device__ float g_wboT[NQ * NQ * CD];
__device__ float g_wboCum[NQ * CD];
__device__ float g_bsum[DD];
__device__ int   g_len[BB];

// ---------------- kPre: transposes, cbn, bsum, len ----------------
__global__ void kPre(const float* __restrict__ W_in, const float* __restrict__ b_in,
                     const float* __restrict__ W_out, const float* __restrict__ b_out,
                     const float* __restrict__ cb, const long long* __restrict__ len64,
                     float* __restrict__ out, int out_size) {
    int tid = blockIdx.x * blockDim.x + threadIdx.x;   // 0..262143
    {   // WinTT[k][m] = W_in[m][k]; coalesced read, scattered write
        int m = tid >> 10, k = tid & 1023;
        g_WinTT[k * 256 + m] = W_in[tid];
    }
    {   // WoT2[mc][d] = W_out[mc>>3][d][mc&7]
        int mc = tid >> 10, d = tid & 1023;
        g_WoT2[tid] = W_out[((size_t)(mc >> 3) * DD + d) * CD + (mc & 7)];
    }
    if (tid < NQ * KCB) {
        const float* row = cb + (size_t)tid * CD;
        float v[8], n2 = 0.0f;
#pragma unroll
        for (int i = 0; i < 8; i++) { v[i] = row[i]; n2 = fmaf(v[i], v[i], n2); }
        float s = fmaxf(__fsqrt_rn(n2), 1e-12f);
#pragma unroll
        for (int i = 0; i < 8; i++) g_cbn[(size_t)tid * CD + i] = __fdiv_rn(v[i], s);
    }
    if (tid < DD) {
        float s = 0.0f;
        for (int n = 0; n < NQ; n++) s += b_out[(size_t)n * DD + tid];
        g_bsum[tid] = s;
    }
    if (tid == 0) {
        long long tmp[BB]; bool ok = true;
        for (int i = 0; i < BB; i++) { tmp[i] = len64[i]; if (tmp[i] < 0 || tmp[i] > TT) ok = false; }
        if (ok) for (int i = 0; i < BB; i++) g_len[i] = (int)tmp[i];
        else { const int* l = (const int*)len64; for (int i = 0; i < BB; i++) g_len[i] = l[i]; }
        if (out_size >= FULL_OUT)
            for (int i = 0; i < BB; i++) out[QOUT_ELEMS + IDX_ELEMS + i] = (float)g_len[i];
    }
}

// ---------------- kWbo: wbo[m][n][c] = W_in^m[c] . b_out^n  (warp per output) ----
__global__ void kWbo(const float* __restrict__ W_in, const float* __restrict__ b_out) {
    int w = (blockIdx.x * blockDim.x + threadIdx.x) >> 5;   // 0..8191
    int lane = threadIdx.x & 31;
    int m = w >> 8, n = (w >> 3) & 31, c = w & 7;
    const float* wr = W_in + ((size_t)m * CD + c) * DD;
    const float* br = b_out + (size_t)n * DD;
    float acc = 0.0f;
#pragma unroll
    for (int i = 0; i < 32; i++)
        acc = fmaf(wr[lane + 32 * i], br[lane + 32 * i], acc);
#pragma unroll
    for (int off = 16; off > 0; off >>= 1)
        acc += __shfl_xor_sync(0xffffffffu, acc, off);
    if (lane == 0) g_wboT[(m * 32 + n) * 8 + c] = acc;
}

// ---------------- kG: G[row][col] = Win[row] . WoT2[col]  (warp per element) ----
__global__ void kG(const float* __restrict__ W_in) {
    int w = (blockIdx.x * blockDim.x + threadIdx.x) >> 5;   // 0..65535
    int lane = threadIdx.x & 31;
    int row = w >> 8, col = w & 255;
    const float* a = W_in  + (size_t)row * DD;
    const float* bvec = g_WoT2 + (size_t)col * DD;
    float acc = 0.0f;
#pragma unroll
    for (int i = 0; i < 32; i++)
        acc = fmaf(a[lane + 32 * i], bvec[lane + 32 * i], acc);
#pragma unroll
    for (int off = 16; off > 0; off >>= 1)
        acc += __shfl_xor_sync(0xffffffffu, acc, off);
    if (lane == 0) g_G[row * 256 + col] = acc;

    int t = blockIdx.x * blockDim.x + threadIdx.x;
    if (t < NQ * CD) {
        int m = t >> 3, c = t & 7;
        float s = 0.0f;
        for (int n = 0; n < m; n++) s += g_wboT[(m * 32 + n) * 8 + c];
        g_wboCum[t] = s;
    }
}

// ---------------- gemmZE: ZE0 = mask * (Win_all x z), tile 64x256x16 ----------------
__global__ void __launch_bounds__(256, 2)
gemmZE(const float* __restrict__ z) {
    __shared__ float As[16 * 64];        // [k][m]
    __shared__ float Bs[16 * 264];       // [k][n], padded
    const int tid = threadIdx.x;
    const int bm  = blockIdx.x * 64;
    const int cb0 = blockIdx.y * 256;
    const int b   = cb0 >> 12, t0 = cb0 & 4095;
    const int len = g_len[b];
    const int tx = tid & 15, ty = tid >> 4;
    const float* zb = z + (size_t)b * DD * TT + t0;

    u64t acc[4][8];
#pragma unroll
    for (int i = 0; i < 4; i++)
#pragma unroll
        for (int p = 0; p < 8; p++) acc[i][p] = 0ull;

    for (int kk = 0; kk < 1024; kk += 16) {
        {   // A: coalesced from WinTT[k][m]
            int row = tid >> 4, c4 = tid & 15;
            *reinterpret_cast<float4*>(&As[row * 64 + c4 * 4]) =
                *reinterpret_cast<const float4*>(&g_WinTT[(size_t)(kk + row) * 256 + bm + c4 * 4]);
            // B: 16 rows x 256 floats, coalesced
#pragma unroll
            for (int it = 0; it < 4; it++) {
                int f = it * 256 + tid, brow = f >> 6, bc4 = f & 63;
                *reinterpret_cast<float4*>(&Bs[brow * 264 + bc4 * 4]) =
                    *reinterpret_cast<const float4*>(zb + (size_t)(kk + brow) * TT + bc4 * 4);
            }
        }
        __syncthreads();
#pragma unroll
        for (int k = 0; k < 16; k++) {
            float4 a4 = *reinterpret_cast<const float4*>(&As[k * 64 + ty * 4]);
            ulonglong2 b0 = *reinterpret_cast<const ulonglong2*>(&Bs[k * 264 + tx * 16]);
            ulonglong2 b1 = *reinterpret_cast<const ulonglong2*>(&Bs[k * 264 + tx * 16 + 4]);
            ulonglong2 b2 = *reinterpret_cast<const ulonglong2*>(&Bs[k * 264 + tx * 16 + 8]);
            ulonglong2 b3 = *reinterpret_cast<const ulonglong2*>(&Bs[k * 264 + tx * 16 + 12]);
            float aa[4] = {a4.x, a4.y, a4.z, a4.w};
#pragma unroll
            for (int i = 0; i < 4; i++) {
                u64t ap = pk2(aa[i], aa[i]);
                fma2(acc[i][0], ap, b0.x); fma2(acc[i][1], ap, b0.y);
                fma2(acc[i][2], ap, b1.x); fma2(acc[i][3], ap, b1.y);
                fma2(acc[i][4], ap, b2.x); fma2(acc[i][5], ap, b2.y);
                fma2(acc[i][6], ap, b3.x); fma2(acc[i][7], ap, b3.y);
            }
        }
        __syncthreads();
    }
#pragma unroll
    for (int i = 0; i < 4; i++) {
        int row = bm + ty * 4 + i;
        float* dst = g_ZE0 + (size_t)row * NCOL + cb0 + tx * 16;
#pragma unroll
        for (int p = 0; p < 4; p++) {
            float2 ua = upk2(acc[i][2 * p]);
            float2 ub = upk2(acc[i][2 * p + 1]);
            int tt = t0 + tx * 16 + 4 * p;
            float4 o;
            o.x = ua.x * ((tt     < len) ? 1.0f : 0.0f);
            o.y = ua.y * ((tt + 1 < len) ? 1.0f : 0.0f);
            o.z = ub.x * ((tt + 2 < len) ? 1.0f : 0.0f);
            o.w = ub.y * ((tt + 3 < len) ? 1.0f : 0.0f);
            *reinterpret_cast<float4*>(dst + 4 * p) = o;
        }
    }
}

// ---------------- rvq_scan v3: double-buffered codebook (unchanged from R12) ----
#define SCAN_SMEM_FLOATS (2*8192 + 4096 + 512)
#define SCAN_SMEM_BYTES  (SCAN_SMEM_FLOATS * 4)

__global__ void __launch_bounds__(256, 2)
rvq_scan(const float* __restrict__ b_in, const float* __restrict__ cb,
         float* __restrict__ out, int out_size) {
    extern __shared__ float smem[];
    float*  sCbn = smem;                          // 2 x 8192
    float*  sG   = smem + 2 * 8192;               // 4096
    float2* sArg = (float2*)(smem + 2 * 8192 + 4096);  // [8][32]

    const int tid  = threadIdx.x;
    const int lane = tid & 31;
    const int warp = tid >> 5;
    const int grp  = warp >> 2;
    const int wq   = warp & 3;
    const int col  = blockIdx.x * 64 + grp * 32 + lane;
    const int b = col >> 12, t = col & 4095;
    const float mask = (t < g_len[b]) ? 1.0f : 0.0f;
    const bool write_idx = (out_size >= QOUT_ELEMS + IDX_ELEMS);

    u64t zqh[32];

#pragma unroll
    for (int it = 0; it < 8; it++) {
        int f = it * 256 + tid;
        *reinterpret_cast<float4*>(&sCbn[f * 4]) =
            *reinterpret_cast<const float4*>(&g_cbn[f * 4]);
    }

    for (int c = 0; c < 4; c++) {
        __syncthreads();
#pragma unroll
        for (int it = 0; it < 4; it++) {
            int f = it * 256 + tid, ri = f >> 4, kq = f & 15;
            *reinterpret_cast<float4*>(&sG[ri * 64 + kq * 4]) =
                *reinterpret_cast<const float4*>(&g_G[(c * 64 + ri) * 256 + c * 64 + kq * 4]);
        }
        __syncthreads();

#pragma unroll
        for (int j = 0; j < 8; j++) {
            const int nq = c * 8 + j;
            const float* cbCur = sCbn + (nq & 1) * 8192;

            if (nq < 31) {
                float* cbNxt = sCbn + ((nq + 1) & 1) * 8192;
#pragma unroll
                for (int it = 0; it < 8; it++) {
                    int f = it * 256 + tid;
                    *reinterpret_cast<float4*>(&cbNxt[f * 4]) =
                        *reinterpret_cast<const float4*>(&g_cbn[(size_t)(nq + 1) * 8192 + f * 4]);
                }
            }

            float e[8];
#pragma unroll
            for (int cc = 0; cc < 8; cc++)
                e[cc] = g_ZE0[(size_t)(nq * 8 + cc) * NCOL + col]
                      + __ldg(b_in + nq * 8 + cc)
                      - mask * __ldg(g_wboCum + nq * 8 + cc);
#pragma unroll
            for (int jj = 0; jj < j; jj++)
#pragma unroll
                for (int ci = 0; ci < 8; ci++) {
                    const u64t* gp = reinterpret_cast<const u64t*>(
                        &sG[(j * 8 + ci) * 64 + jj * 8]);
                    u64t a = mul2(gp[0], zqh[jj * 4 + 0]);
                    fma2(a, gp[1], zqh[jj * 4 + 1]);
                    fma2(a, gp[2], zqh[jj * 4 + 2]);
                    fma2(a, gp[3], zqh[jj * 4 + 3]);
                    float2 u = upk2(a);
                    e[ci] -= (u.x + u.y);
                }
            u64t zep[4];
#pragma unroll
            for (int p = 0; p < 4; p++) zep[p] = pk2(e[2 * p], e[2 * p + 1]);

            float best = -3.4e38f; int bk = 0;
            const ulonglong2* cb2 = reinterpret_cast<const ulonglong2*>(cbCur) + wq * 512;
#pragma unroll 4
            for (int kq2 = 0; kq2 < 256; kq2++) {
                ulonglong2 cA = cb2[kq2 * 2], cB = cb2[kq2 * 2 + 1];
                u64t dp = mul2(zep[0], cA.x);
                fma2(dp, zep[1], cA.y);
                fma2(dp, zep[2], cB.x);
                fma2(dp, zep[3], cB.y);
                float2 u = upk2(dp);
                float d = u.x + u.y;
                if (d > best) { best = d; bk = wq * 256 + kq2; }
            }
            sArg[warp * 32 + lane] = make_float2(best, __int_as_float(bk));
            __syncthreads();

            float2 a0 = sArg[(grp * 4 + 0) * 32 + lane];
            float bb = a0.x; int bki = __float_as_int(a0.y);
#pragma unroll
            for (int q = 1; q < 4; q++) {
                float2 aq = sArg[(grp * 4 + q) * 32 + lane];
                if (aq.x > bb) { bb = aq.x; bki = __float_as_int(aq.y); }
            }

            const ulonglong2* pcb = reinterpret_cast<const ulonglong2*>(
                cb + ((size_t)nq * KCB + bki) * CD);
            ulonglong2 qa = __ldg(pcb), qb = __ldg(pcb + 1);
            u64t mm = pk2(mask, mask);
            zqh[j * 4 + 0] = mul2(qa.x, mm);
            zqh[j * 4 + 1] = mul2(qa.y, mm);
            zqh[j * 4 + 2] = mul2(qb.x, mm);
            zqh[j * 4 + 3] = mul2(qb.y, mm);

            if (wq == 0) {
#pragma unroll
                for (int p = 0; p < 4; p++) {
                    float2 u = upk2(zqh[j * 4 + p]);
                    g_ZQ[(size_t)(nq * 8 + 2 * p) * NCOL + col] = u.x;
                    g_ZQ[(size_t)(nq * 8 + 2 * p + 1) * NCOL + col] = u.y;
                }
                if (write_idx)
                    out[QOUT_ELEMS + (size_t)(nq * BB + b) * TT + t] = (float)bki;
            }
            __syncthreads();
        }

        for (int fc = c + 1; fc < 4; fc++) {
            __syncthreads();
#pragma unroll
            for (int it = 0; it < 4; it++) {
                int f = it * 256 + tid, ri = f >> 4, kq = f & 15;
                *reinterpret_cast<float4*>(&sG[ri * 64 + kq * 4]) =
                    *reinterpret_cast<const float4*>(&g_G[(fc * 64 + ri) * 256 + c * 64 + kq * 4]);
            }
            __syncthreads();
#pragma unroll 4
            for (int r16 = 0; r16 < 16; r16++) {
                int r = wq * 16 + r16;
                const u64t* gp = reinterpret_cast<const u64t*>(&sG[r * 64]);
                u64t a = mul2(gp[0], zqh[0]);
#pragma unroll
                for (int q = 1; q < 32; q++) fma2(a, gp[q], zqh[q]);
                float2 u = upk2(a);
                size_t idx = (size_t)(fc * 64 + r) * NCOL + col;
                g_ZE0[idx] -= (u.x + u.y);
            }
        }
    }
}

// ---------------- gemmQ: qout = WoT x ZQ + mask*bsum, tile 64x256x16 ----------------
__global__ void __launch_bounds__(256, 2)
gemmQ(float* __restrict__ out, int out_size) {
    __shared__ float As[16 * 64];
    __shared__ float Bs[16 * 264];
    if (out_size < QOUT_ELEMS) return;
    const int tid = threadIdx.x;
    const int bm  = blockIdx.x * 64;       // d-tile
    const int cb0 = blockIdx.y * 256;
    const int b   = cb0 >> 12, t0 = cb0 & 4095;
    const int len = g_len[b];
    const int tx = tid & 15, ty = tid >> 4;

    u64t acc[4][8];
#pragma unroll
    for (int i = 0; i < 4; i++)
#pragma unroll
        for (int p = 0; p < 8; p++) acc[i][p] = 0ull;

    for (int kk = 0; kk < 256; kk += 16) {
        {   // A: coalesced from WoT2[k=mc][m=d]
            int row = tid >> 4, c4 = tid & 15;
            *reinterpret_cast<float4*>(&As[row * 64 + c4 * 4]) =
                *reinterpret_cast<const float4*>(&g_WoT2[(size_t)(kk + row) * DD + bm + c4 * 4]);
#pragma unroll
            for (int it = 0; it < 4; it++) {
                int f = it * 256 + tid, brow = f >> 6, bc4 = f & 63;
                *reinterpret_cast<float4*>(&Bs[brow * 264 + bc4 * 4]) =
                    *reinterpret_cast<const float4*>(g_ZQ + (size_t)(kk + brow) * NCOL + cb0 + bc4 * 4);
            }
        }
        __syncthreads();
#pragma unroll
        for (int k = 0; k < 16; k++) {
            float4 a4 = *reinterpret_cast<const float4*>(&As[k * 64 + ty * 4]);
            ulonglong2 b0 = *reinterpret_cast<const ulonglong2*>(&Bs[k * 264 + tx * 16]);
            ulonglong2 b1 = *reinterpret_cast<const ulonglong2*>(&Bs[k * 264 + tx * 16 + 4]);
            ulonglong2 b2 = *reinterpret_cast<const ulonglong2*>(&Bs[k * 264 + tx * 16 + 8]);
            ulonglong2 b3 = *reinterpret_cast<const ulonglong2*>(&Bs[k * 264 + tx * 16 + 12]);
            float aa[4] = {a4.x, a4.y, a4.z, a4.w};
#pragma unroll
            for (int i = 0; i < 4; i++) {
                u64t ap = pk2(aa[i], aa[i]);
                fma2(acc[i][0], ap, b0.x); fma2(acc[i][1], ap, b0.y);
                fma2(acc[i][2], ap, b1.x); fma2(acc[i][3], ap, b1.y);
                fma2(acc[i][4], ap, b2.x); fma2(acc[i][5], ap, b2.y);
                fma2(acc[i][6], ap, b3.x); fma2(acc[i][7], ap, b3.y);
            }
        }
        __syncthreads();
    }
#pragma unroll
    for (int i = 0; i < 4; i++) {
        int d = bm + ty * 4 + i;
        float bs = __ldg(g_bsum + d);
        float* dst = out + (size_t)b * DD * TT + (size_t)d * TT + t0 + tx * 16;
#pragma unroll
        for (int p = 0; p < 4; p++) {
            float2 ua = upk2(acc[i][2 * p]);
            float2 ub = upk2(acc[i][2 * p + 1]);
            int tt = t0 + tx * 16 + 4 * p;
            float m0 = (tt     < len) ? 1.0f : 0.0f;
            float m1 = (tt + 1 < len) ? 1.0f : 0.0f;
            float m2 = (tt + 2 < len) ? 1.0f : 0.0f;
            float m3 = (tt + 3 < len) ? 1.0f : 0.0f;
            float4 o;
            o.x = (ua.x + m0 * bs) * m0;
            o.y = (ua.y + m1 * bs) * m1;
            o.z = (ub.x + m2 * bs) * m2;
            o.w = (ub.y + m3 * bs) * m3;
            *reinterpret_cast<float4*>(dst + 4 * p) = o;
        }
    }
}

// ---------------------------------------------------------------------------
extern "C" void kernel_launch(void* const* d_in, const int* in_sizes, int n_in,
                              void* d_out, int out_size) {
    const float*     z     = (const float*)d_in[0];
    const long long* len   = (const long long*)d_in[1];
    const float*     W_in  = (const float*)d_in[2];
    const float*     b_in  = (const float*)d_in[3];
    const float*     W_out = (const float*)d_in[4];
    const float*     b_out = (const float*)d_in[5];
    const float*     cbk   = (const float*)d_in[6];
    float* out = (float*)d_out;

    cudaFuncSetAttribute(rvq_scan,
                         cudaFuncAttributeMaxDynamicSharedMemorySize, SCAN_SMEM_BYTES);

    kPre<<<1024, 256>>>(W_in, b_in, W_out, b_out, cbk, len, out, out_size);
    kWbo<<<1024, 256>>>(W_in, b_out);
    kG<<<8192, 256>>>(W_in);
    gemmZE<<<dim3(4, 128), 256>>>(z);
    rvq_scan<<<512, 256, SCAN_SMEM_BYTES>>>(b_in, cbk, out, out_size);
    gemmQ<<<dim3(16, 128), 256>>>(out, out_size);
}

// round 14
// speedup vs baseline: 3.1546x; 3.1546x over previous
#include <cuda_runtime.h>
#include <cstdint>

#define NQ   32
#define KCB  1024
#define CD   8
#define DD   1024
#define TT   4096
#define BB   8
#define NCOL (BB * TT)

#define QOUT_ELEMS (BB * DD * TT)
#define IDX_ELEMS  (NQ * BB * TT)
#define FULL_OUT   (QOUT_ELEMS + IDX_ELEMS + BB)

typedef unsigned long long u64t;

__device__ __forceinline__ u64t pk2(float a, float b) {
    u64t r; asm("mov.b64 %0,{%1,%2};" : "=l"(r) : "f"(a), "f"(b)); return r;
}
__device__ __forceinline__ float2 upk2(u64t v) {
    float2 r; asm("mov.b64 {%0,%1},%2;" : "=f"(r.x), "=f"(r.y) : "l"(v)); return r;
}
__device__ __forceinline__ void fma2(u64t& d, u64t a, u64t b) {
    asm("fma.rn.f32x2 %0,%1,%2,%0;" : "+l"(d) : "l"(a), "l"(b));
}
__device__ __forceinline__ u64t mul2(u64t a, u64t b) {
    u64t r; asm("mul.rn.f32x2 %0,%1,%2;" : "=l"(r) : "l"(a), "l"(b)); return r;
}

// scratch (device globals; zero-alloc rule)
__device__ float g_ZE0[256 * NCOL];      // [mc][col]
__device__ float g_ZQ [256 * NCOL];      // [mc][col], masked zq
__device__ float g_G  [256 * 256];
__device__ float g_WinTT[DD * 256];      // [k][m]  A^T for gemmZE
__device__ float g_WoT2 [256 * DD];      // [mc][d] A^T for gemmQ + kG operand
__device__ float g_cbn[NQ * KCB * CD];
__device__ float g_wboT[NQ * NQ * CD];
__device__ float g_wboCum[NQ * CD];
__device__ float g_bsum[DD];
__device__ int   g_len[BB];

// ---------------- kPre: transposes, cbn, bsum, len ----------------
__global__ void kPre(const float* __restrict__ W_in, const float* __restrict__ b_in,
                     const float* __restrict__ W_out, const float* __restrict__ b_out,
                     const float* __restrict__ cb, const long long* __restrict__ len64,
                     float* __restrict__ out, int out_size) {
    int tid = blockIdx.x * blockDim.x + threadIdx.x;   // 0..262143
    {   // WinTT[k][m] = W_in[m][k]
        int m = tid >> 10, k = tid & 1023;
        g_WinTT[k * 256 + m] = W_in[tid];
    }
    {   // WoT2[mc][d] = W_out[mc>>3][d][mc&7]
        int mc = tid >> 10, d = tid & 1023;
        g_WoT2[tid] = W_out[((size_t)(mc >> 3) * DD + d) * CD + (mc & 7)];
    }
    if (tid < NQ * KCB) {
        const float* row = cb + (size_t)tid * CD;
        float v[8], n2 = 0.0f;
#pragma unroll
        for (int i = 0; i < 8; i++) { v[i] = row[i]; n2 = fmaf(v[i], v[i], n2); }
        float s = fmaxf(__fsqrt_rn(n2), 1e-12f);
#pragma unroll
        for (int i = 0; i < 8; i++) g_cbn[(size_t)tid * CD + i] = __fdiv_rn(v[i], s);
    }
    if (tid < DD) {
        float s = 0.0f;
        for (int n = 0; n < NQ; n++) s += b_out[(size_t)n * DD + tid];
        g_bsum[tid] = s;
    }
    if (tid == 0) {
        long long tmp[BB]; bool ok = true;
        for (int i = 0; i < BB; i++) { tmp[i] = len64[i]; if (tmp[i] < 0 || tmp[i] > TT) ok = false; }
        if (ok) for (int i = 0; i < BB; i++) g_len[i] = (int)tmp[i];
        else { const int* l = (const int*)len64; for (int i = 0; i < BB; i++) g_len[i] = l[i]; }
        if (out_size >= FULL_OUT)
            for (int i = 0; i < BB; i++) out[QOUT_ELEMS + IDX_ELEMS + i] = (float)g_len[i];
    }
}

// ---------------- kWbo: wbo[m][n][c] = W_in^m[c] . b_out^n  (warp per output) ----
__global__ void kWbo(const float* __restrict__ W_in, const float* __restrict__ b_out) {
    int w = (blockIdx.x * blockDim.x + threadIdx.x) >> 5;   // 0..8191
    int lane = threadIdx.x & 31;
    int m = w >> 8, n = (w >> 3) & 31, c = w & 7;
    const float* wr = W_in + ((size_t)m * CD + c) * DD;
    const float* br = b_out + (size_t)n * DD;
    float acc = 0.0f;
#pragma unroll
    for (int i = 0; i < 32; i++)
        acc = fmaf(wr[lane + 32 * i], br[lane + 32 * i], acc);
#pragma unroll
    for (int off = 16; off > 0; off >>= 1)
        acc += __shfl_xor_sync(0xffffffffu, acc, off);
    if (lane == 0) g_wboT[(m * 32 + n) * 8 + c] = acc;
}

// ---------------- kG: G[row][col] = Win[row] . WoT2[col]  (warp per element) ----
__global__ void kG(const float* __restrict__ W_in) {
    int w = (blockIdx.x * blockDim.x + threadIdx.x) >> 5;   // 0..65535
    int lane = threadIdx.x & 31;
    int row = w >> 8, col = w & 255;
    const float* a = W_in  + (size_t)row * DD;
    const float* bvec = g_WoT2 + (size_t)col * DD;
    float acc = 0.0f;
#pragma unroll
    for (int i = 0; i < 32; i++)
        acc = fmaf(a[lane + 32 * i], bvec[lane + 32 * i], acc);
#pragma unroll
    for (int off = 16; off > 0; off >>= 1)
        acc += __shfl_xor_sync(0xffffffffu, acc, off);
    if (lane == 0) g_G[row * 256 + col] = acc;

    int t = blockIdx.x * blockDim.x + threadIdx.x;
    if (t < NQ * CD) {
        int m = t >> 3, c = t & 7;
        float s = 0.0f;
        for (int n = 0; n < m; n++) s += g_wboT[(m * 32 + n) * 8 + c];
        g_wboCum[t] = s;
    }
}

// ---------------- gemmZE: ZE0 = mask*(Win_all x z), tile 64x256x16, m->warp n->lane ----
__global__ void __launch_bounds__(256, 2)
gemmZE(const float* __restrict__ z) {
    __shared__ float As[16 * 64];        // [k][m]
    __shared__ float Bs[16 * 264];       // [k][n], padded
    const int tid  = threadIdx.x;
    const int wm   = tid >> 5;           // warp -> 8 m-rows
    const int lane = tid & 31;           // lane -> n = lane*4 (+128)
    const int bm  = blockIdx.x * 64;
    const int cb0 = blockIdx.y * 256;
    const int b   = cb0 >> 12, t0 = cb0 & 4095;
    const int len = g_len[b];
    const float* zb = z + (size_t)b * DD * TT + t0;

    u64t acc[8][4];
#pragma unroll
    for (int i = 0; i < 8; i++)
#pragma unroll
        for (int p = 0; p < 4; p++) acc[i][p] = 0ull;

    for (int kk = 0; kk < 1024; kk += 16) {
        {   // A staging: coalesced from WinTT[k][m]
            int row = tid >> 4, c4 = tid & 15;
            *reinterpret_cast<float4*>(&As[row * 64 + c4 * 4]) =
                *reinterpret_cast<const float4*>(&g_WinTT[(size_t)(kk + row) * 256 + bm + c4 * 4]);
            // B staging: 16 rows x 256 floats, coalesced
#pragma unroll
            for (int it = 0; it < 4; it++) {
                int f = it * 256 + tid, brow = f >> 6, bc4 = f & 63;
                *reinterpret_cast<float4*>(&Bs[brow * 264 + bc4 * 4]) =
                    *reinterpret_cast<const float4*>(zb + (size_t)(kk + brow) * TT + bc4 * 4);
            }
        }
        __syncthreads();
#pragma unroll
        for (int k = 0; k < 16; k++) {
            const float* ar = &As[k * 64 + wm * 8];
            float4 a0 = *reinterpret_cast<const float4*>(ar);       // broadcast
            float4 a1 = *reinterpret_cast<const float4*>(ar + 4);   // broadcast
            ulonglong2 bA = *reinterpret_cast<const ulonglong2*>(&Bs[k * 264 + lane * 4]);
            ulonglong2 bB = *reinterpret_cast<const ulonglong2*>(&Bs[k * 264 + 128 + lane * 4]);
            float aa[8] = {a0.x, a0.y, a0.z, a0.w, a1.x, a1.y, a1.z, a1.w};
#pragma unroll
            for (int i = 0; i < 8; i++) {
                u64t ap = pk2(aa[i], aa[i]);
                fma2(acc[i][0], ap, bA.x); fma2(acc[i][1], ap, bA.y);
                fma2(acc[i][2], ap, bB.x); fma2(acc[i][3], ap, bB.y);
            }
        }
        __syncthreads();
    }
    // epilogue: n = cb0 + lane*4 (+128)
    {
        int tA = t0 + lane * 4, tB = tA + 128;
        float mA0 = (tA     < len) ? 1.0f : 0.0f;
        float mA1 = (tA + 1 < len) ? 1.0f : 0.0f;
        float mA2 = (tA + 2 < len) ? 1.0f : 0.0f;
        float mA3 = (tA + 3 < len) ? 1.0f : 0.0f;
        float mB0 = (tB     < len) ? 1.0f : 0.0f;
        float mB1 = (tB + 1 < len) ? 1.0f : 0.0f;
        float mB2 = (tB + 2 < len) ? 1.0f : 0.0f;
        float mB3 = (tB + 3 < len) ? 1.0f : 0.0f;
#pragma unroll
        for (int i = 0; i < 8; i++) {
            int row = bm + wm * 8 + i;
            float* dst = g_ZE0 + (size_t)row * NCOL + cb0 + lane * 4;
            float2 u0 = upk2(acc[i][0]), u1 = upk2(acc[i][1]);
            float2 u2 = upk2(acc[i][2]), u3 = upk2(acc[i][3]);
            float4 oA = make_float4(u0.x * mA0, u0.y * mA1, u1.x * mA2, u1.y * mA3);
            float4 oB = make_float4(u2.x * mB0, u2.y * mB1, u3.x * mB2, u3.y * mB3);
            *reinterpret_cast<float4*>(dst)       = oA;
            *reinterpret_cast<float4*>(dst + 128) = oB;
        }
    }
}

// ---------------- rvq_scan v3: double-buffered codebook (unchanged, passing) ----
#define SCAN_SMEM_FLOATS (2*8192 + 4096 + 512)
#define SCAN_SMEM_BYTES  (SCAN_SMEM_FLOATS * 4)

__global__ void __launch_bounds__(256, 2)
rvq_scan(const float* __restrict__ b_in, const float* __restrict__ cb,
         float* __restrict__ out, int out_size) {
    extern __shared__ float smem[];
    float*  sCbn = smem;                          // 2 x 8192
    float*  sG   = smem + 2 * 8192;               // 4096
    float2* sArg = (float2*)(smem + 2 * 8192 + 4096);  // [8][32]

    const int tid  = threadIdx.x;
    const int lane = tid & 31;
    const int warp = tid >> 5;
    const int grp  = warp >> 2;
    const int wq   = warp & 3;
    const int col  = blockIdx.x * 64 + grp * 32 + lane;
    const int b = col >> 12, t = col & 4095;
    const float mask = (t < g_len[b]) ? 1.0f : 0.0f;
    const bool write_idx = (out_size >= QOUT_ELEMS + IDX_ELEMS);

    u64t zqh[32];

#pragma unroll
    for (int it = 0; it < 8; it++) {
        int f = it * 256 + tid;
        *reinterpret_cast<float4*>(&sCbn[f * 4]) =
            *reinterpret_cast<const float4*>(&g_cbn[f * 4]);
    }

    for (int c = 0; c < 4; c++) {
        __syncthreads();
#pragma unroll
        for (int it = 0; it < 4; it++) {
            int f = it * 256 + tid, ri = f >> 4, kq = f & 15;
            *reinterpret_cast<float4*>(&sG[ri * 64 + kq * 4]) =
                *reinterpret_cast<const float4*>(&g_G[(c * 64 + ri) * 256 + c * 64 + kq * 4]);
        }
        __syncthreads();

#pragma unroll
        for (int j = 0; j < 8; j++) {
            const int nq = c * 8 + j;
            const float* cbCur = sCbn + (nq & 1) * 8192;

            if (nq < 31) {
                float* cbNxt = sCbn + ((nq + 1) & 1) * 8192;
#pragma unroll
                for (int it = 0; it < 8; it++) {
                    int f = it * 256 + tid;
                    *reinterpret_cast<float4*>(&cbNxt[f * 4]) =
                        *reinterpret_cast<const float4*>(&g_cbn[(size_t)(nq + 1) * 8192 + f * 4]);
                }
            }

            float e[8];
#pragma unroll
            for (int cc = 0; cc < 8; cc++)
                e[cc] = g_ZE0[(size_t)(nq * 8 + cc) * NCOL + col]
                      + __ldg(b_in + nq * 8 + cc)
                      - mask * __ldg(g_wboCum + nq * 8 + cc);
#pragma unroll
            for (int jj = 0; jj < j; jj++)
#pragma unroll
                for (int ci = 0; ci < 8; ci++) {
                    const u64t* gp = reinterpret_cast<const u64t*>(
                        &sG[(j * 8 + ci) * 64 + jj * 8]);
                    u64t a = mul2(gp[0], zqh[jj * 4 + 0]);
                    fma2(a, gp[1], zqh[jj * 4 + 1]);
                    fma2(a, gp[2], zqh[jj * 4 + 2]);
                    fma2(a, gp[3], zqh[jj * 4 + 3]);
                    float2 u = upk2(a);
                    e[ci] -= (u.x + u.y);
                }
            u64t zep[4];
#pragma unroll
            for (int p = 0; p < 4; p++) zep[p] = pk2(e[2 * p], e[2 * p + 1]);

            float best = -3.4e38f; int bk = 0;
            const ulonglong2* cb2 = reinterpret_cast<const ulonglong2*>(cbCur) + wq * 512;
#pragma unroll 4
            for (int kq2 = 0; kq2 < 256; kq2++) {
                ulonglong2 cA = cb2[kq2 * 2], cB = cb2[kq2 * 2 + 1];
                u64t dp = mul2(zep[0], cA.x);
                fma2(dp, zep[1], cA.y);
                fma2(dp, zep[2], cB.x);
                fma2(dp, zep[3], cB.y);
                float2 u = upk2(dp);
                float d = u.x + u.y;
                if (d > best) { best = d; bk = wq * 256 + kq2; }
            }
            sArg[warp * 32 + lane] = make_float2(best, __int_as_float(bk));
            __syncthreads();

            float2 a0 = sArg[(grp * 4 + 0) * 32 + lane];
            float bb = a0.x; int bki = __float_as_int(a0.y);
#pragma unroll
            for (int q = 1; q < 4; q++) {
                float2 aq = sArg[(grp * 4 + q) * 32 + lane];
                if (aq.x > bb) { bb = aq.x; bki = __float_as_int(aq.y); }
            }

            const ulonglong2* pcb = reinterpret_cast<const ulonglong2*>(
                cb + ((size_t)nq * KCB + bki) * CD);
            ulonglong2 qa = __ldg(pcb), qb = __ldg(pcb + 1);
            u64t mm = pk2(mask, mask);
            zqh[j * 4 + 0] = mul2(qa.x, mm);
            zqh[j * 4 + 1] = mul2(qa.y, mm);
            zqh[j * 4 + 2] = mul2(qb.x, mm);
            zqh[j * 4 + 3] = mul2(qb.y, mm);

            if (wq == 0) {
#pragma unroll
                for (int p = 0; p < 4; p++) {
                    float2 u = upk2(zqh[j * 4 + p]);
                    g_ZQ[(size_t)(nq * 8 + 2 * p) * NCOL + col] = u.x;
                    g_ZQ[(size_t)(nq * 8 + 2 * p + 1) * NCOL + col] = u.y;
                }
                if (write_idx)
                    out[QOUT_ELEMS + (size_t)(nq * BB + b) * TT + t] = (float)bki;
            }
            __syncthreads();
        }

        for (int fc = c + 1; fc < 4; fc++) {
            __syncthreads();
#pragma unroll
            for (int it = 0; it < 4; it++) {
                int f = it * 256 + tid, ri = f >> 4, kq = f & 15;
                *reinterpret_cast<float4*>(&sG[ri * 64 + kq * 4]) =
                    *reinterpret_cast<const float4*>(&g_G[(fc * 64 + ri) * 256 + c * 64 + kq * 4]);
            }
            __syncthreads();
#pragma unroll 4
            for (int r16 = 0; r16 < 16; r16++) {
                int r = wq * 16 + r16;
                const u64t* gp = reinterpret_cast<const u64t*>(&sG[r * 64]);
                u64t a = mul2(gp[0], zqh[0]);
#pragma unroll
                for (int q = 1; q < 32; q++) fma2(a, gp[q], zqh[q]);
                float2 u = upk2(a);
                size_t idx = (size_t)(fc * 64 + r) * NCOL + col;
                g_ZE0[idx] -= (u.x + u.y);
            }
        }
    }
}

// ---------------- gemmQ: qout = WoT x ZQ + mask*bsum, tile 64x256x16, m->warp ----
__global__ void __launch_bounds__(256, 2)
gemmQ(float* __restrict__ out, int out_size) {
    __shared__ float As[16 * 64];
    __shared__ float Bs[16 * 264];
    if (out_size < QOUT_ELEMS) return;
    const int tid  = threadIdx.x;
    const int wm   = tid >> 5;
    const int lane = tid & 31;
    const int bm  = blockIdx.x * 64;       // d-tile
    const int cb0 = blockIdx.y * 256;
    const int b   = cb0 >> 12, t0 = cb0 & 4095;
    const int len = g_len[b];

    u64t acc[8][4];
#pragma unroll
    for (int i = 0; i < 8; i++)
#pragma unroll
        for (int p = 0; p < 4; p++) acc[i][p] = 0ull;

    for (int kk = 0; kk < 256; kk += 16) {
        {   // A: coalesced from WoT2[k=mc][m=d]
            int row = tid >> 4, c4 = tid & 15;
            *reinterpret_cast<float4*>(&As[row * 64 + c4 * 4]) =
                *reinterpret_cast<const float4*>(&g_WoT2[(size_t)(kk + row) * DD + bm + c4 * 4]);
#pragma unroll
            for (int it = 0; it < 4; it++) {
                int f = it * 256 + tid, brow = f >> 6, bc4 = f & 63;
                *reinterpret_cast<float4*>(&Bs[brow * 264 + bc4 * 4]) =
                    *reinterpret_cast<const float4*>(g_ZQ + (size_t)(kk + brow) * NCOL + cb0 + bc4 * 4);
            }
        }
        __syncthreads();
#pragma unroll
        for (int k = 0; k < 16; k++) {
            const float* ar = &As[k * 64 + wm * 8];
            float4 a0 = *reinterpret_cast<const float4*>(ar);
            float4 a1 = *reinterpret_cast<const float4*>(ar + 4);
            ulonglong2 bA = *reinterpret_cast<const ulonglong2*>(&Bs[k * 264 + lane * 4]);
            ulonglong2 bB = *reinterpret_cast<const ulonglong2*>(&Bs[k * 264 + 128 + lane * 4]);
            float aa[8] = {a0.x, a0.y, a0.z, a0.w, a1.x, a1.y, a1.z, a1.w};
#pragma unroll
            for (int i = 0; i < 8; i++) {
                u64t ap = pk2(aa[i], aa[i]);
                fma2(acc[i][0], ap, bA.x); fma2(acc[i][1], ap, bA.y);
                fma2(acc[i][2], ap, bB.x); fma2(acc[i][3], ap, bB.y);
            }
        }
        __syncthreads();
    }
    {
        int tA = t0 + lane * 4, tB = tA + 128;
        float mA0 = (tA     < len) ? 1.0f : 0.0f;
        float mA1 = (tA + 1 < len) ? 1.0f : 0.0f;
        float mA2 = (tA + 2 < len) ? 1.0f : 0.0f;
        float mA3 = (tA + 3 < len) ? 1.0f : 0.0f;
        float mB0 = (tB     < len) ? 1.0f : 0.0f;
        float mB1 = (tB + 1 < len) ? 1.0f : 0.0f;
        float mB2 = (tB + 2 < len) ? 1.0f : 0.0f;
        float mB3 = (tB + 3 < len) ? 1.0f : 0.0f;
#pragma unroll
        for (int i = 0; i < 8; i++) {
            int d = bm + wm * 8 + i;
            float bs = __ldg(g_bsum + d);
            float* dst = out + (size_t)b * DD * TT + (size_t)d * TT + t0 + lane * 4;
            float2 u0 = upk2(acc[i][0]), u1 = upk2(acc[i][1]);
            float2 u2 = upk2(acc[i][2]), u3 = upk2(acc[i][3]);
            float4 oA, oB;
            oA.x = (u0.x + mA0 * bs) * mA0;
            oA.y = (u0.y + mA1 * bs) * mA1;
            oA.z = (u1.x + mA2 * bs) * mA2;
            oA.w = (u1.y + mA3 * bs) * mA3;
            oB.x = (u2.x + mB0 * bs) * mB0;
            oB.y = (u2.y + mB1 * bs) * mB1;
            oB.z = (u3.x + mB2 * bs) * mB2;
            oB.w = (u3.y + mB3 * bs) * mB3;
            *reinterpret_cast<float4*>(dst)       = oA;
            *reinterpret_cast<float4*>(dst + 128) = oB;
        }
    }
}

// ---------------------------------------------------------------------------
extern "C" void kernel_launch(void* const* d_in, const int* in_sizes, int n_in,
                              void* d_out, int out_size) {
    const float*     z     = (const float*)d_in[0];
    const long long* len   = (const long long*)d_in[1];
    const float*     W_in  = (const float*)d_in[2];
    const float*     b_in  = (const float*)d_in[3];
    const float*     W_out = (const float*)d_in[4];
    const float*     b_out = (const float*)d_in[5];
    const float*     cbk   = (const float*)d_in[6];
    float* out = (float*)d_out;

    cudaFuncSetAttribute(rvq_scan,
                         cudaFuncAttributeMaxDynamicSharedMemorySize, SCAN_SMEM_BYTES);

    kPre<<<1024, 256>>>(W_in, b_in, W_out, b_out, cbk, len, out, out_size);
    kWbo<<<1024, 256>>>(W_in, b_out);
    kG<<<8192, 256>>>(W_in);
    gemmZE<<<dim3(4, 128), 256>>>(z);
    rvq_scan<<<512, 256, SCAN_SMEM_BYTES>>>(b_in, cbk, out, out_size);
    gemmQ<<<dim3(16, 128), 256>>>(out, out_size);
}

// round 15
// speedup vs baseline: 3.3301x; 1.0556x over previous
#include <cuda_runtime.h>
#include <cstdint>

#define NQ   32
#define KCB  1024
#define CD   8
#define DD   1024
#define TT   4096
#define BB   8
#define NCOL (BB * TT)

#define QOUT_ELEMS (BB * DD * TT)
#define IDX_ELEMS  (NQ * BB * TT)
#define FULL_OUT   (QOUT_ELEMS + IDX_ELEMS + BB)

typedef unsigned long long u64t;

__device__ __forceinline__ u64t pk2(float a, float b) {
    u64t r; asm("mov.b64 %0,{%1,%2};" : "=l"(r) : "f"(a), "f"(b)); return r;
}
__device__ __forceinline__ float2 upk2(u64t v) {
    float2 r; asm("mov.b64 {%0,%1},%2;" : "=f"(r.x), "=f"(r.y) : "l"(v)); return r;
}
__device__ __forceinline__ void fma2(u64t& d, u64t a, u64t b) {
    asm("fma.rn.f32x2 %0,%1,%2,%0;" : "+l"(d) : "l"(a), "l"(b));
}
__device__ __forceinline__ u64t mul2(u64t a, u64t b) {
    u64t r; asm("mul.rn.f32x2 %0,%1,%2;" : "=l"(r) : "l"(a), "l"(b)); return r;
}

// ---- cp.async helpers ----
__device__ __forceinline__ uint32_t s2u(const void* p) {
    uint32_t a;
    asm("{ .reg .u64 t; cvta.to.shared.u64 t, %1; cvt.u32.u64 %0, t; }"
        : "=r"(a) : "l"(p));
    return a;
}
__device__ __forceinline__ void cpa16(uint32_t dst, const void* src) {
    asm volatile("cp.async.ca.shared.global [%0], [%1], 16;" :: "r"(dst), "l"(src));
}
__device__ __forceinline__ void cpa_commit() {
    asm volatile("cp.async.commit_group;");
}
__device__ __forceinline__ void cpa_wait_all() {
    asm volatile("cp.async.wait_group 0;");
}

// scratch (device globals; zero-alloc rule)
__device__ float g_ZE0[256 * NCOL];      // [mc][col]
__device__ float g_ZQ [256 * NCOL];      // [mc][col], masked zq
__device__ float g_G  [256 * 256];
__device__ float g_WinTT[DD * 256];      // [k][m]  A^T for gemmZE
__device__ float g_WoT2 [256 * DD];      // [mc][d] A^T for gemmQ + kG operand
__device__ float g_cbn[NQ * KCB * CD];
__device__ float g_wboT[NQ * NQ * CD];
__device__ float g_wboCum[NQ * CD];
__device__ float g_bsum[DD];
__device__ int   g_len[BB];

// ---------------- kPre: transposes, cbn, bsum, len ----------------
__global__ void kPre(const float* __restrict__ W_in, const float* __restrict__ b_in,
                     const float* __restrict__ W_out, const float* __restrict__ b_out,
                     const float* __restrict__ cb, const long long* __restrict__ len64,
                     float* __restrict__ out, int out_size) {
    int tid = blockIdx.x * blockDim.x + threadIdx.x;   // 0..262143
    {   // WinTT[k][m] = W_in[m][k]
        int m = tid >> 10, k = tid & 1023;
        g_WinTT[k * 256 + m] = W_in[tid];
    }
    {   // WoT2[mc][d] = W_out[mc>>3][d][mc&7]
        int mc = tid >> 10, d = tid & 1023;
        g_WoT2[tid] = W_out[((size_t)(mc >> 3) * DD + d) * CD + (mc & 7)];
    }
    if (tid < NQ * KCB) {
        const float* row = cb + (size_t)tid * CD;
        float v[8], n2 = 0.0f;
#pragma unroll
        for (int i = 0; i < 8; i++) { v[i] = row[i]; n2 = fmaf(v[i], v[i], n2); }
        float s = fmaxf(__fsqrt_rn(n2), 1e-12f);
#pragma unroll
        for (int i = 0; i < 8; i++) g_cbn[(size_t)tid * CD + i] = __fdiv_rn(v[i], s);
    }
    if (tid < DD) {
        float s = 0.0f;
        for (int n = 0; n < NQ; n++) s += b_out[(size_t)n * DD + tid];
        g_bsum[tid] = s;
    }
    if (tid == 0) {
        long long tmp[BB]; bool ok = true;
        for (int i = 0; i < BB; i++) { tmp[i] = len64[i]; if (tmp[i] < 0 || tmp[i] > TT) ok = false; }
        if (ok) for (int i = 0; i < BB; i++) g_len[i] = (int)tmp[i];
        else { const int* l = (const int*)len64; for (int i = 0; i < BB; i++) g_len[i] = l[i]; }
        if (out_size >= FULL_OUT)
            for (int i = 0; i < BB; i++) out[QOUT_ELEMS + IDX_ELEMS + i] = (float)g_len[i];
    }
}

// ---------------- kWbo: wbo[m][n][c] = W_in^m[c] . b_out^n  (warp per output) ----
__global__ void kWbo(const float* __restrict__ W_in, const float* __restrict__ b_out) {
    int w = (blockIdx.x * blockDim.x + threadIdx.x) >> 5;   // 0..8191
    int lane = threadIdx.x & 31;
    int m = w >> 8, n = (w >> 3) & 31, c = w & 7;
    const float* wr = W_in + ((size_t)m * CD + c) * DD;
    const float* br = b_out + (size_t)n * DD;
    float acc = 0.0f;
#pragma unroll
    for (int i = 0; i < 32; i++)
        acc = fmaf(wr[lane + 32 * i], br[lane + 32 * i], acc);
#pragma unroll
    for (int off = 16; off > 0; off >>= 1)
        acc += __shfl_xor_sync(0xffffffffu, acc, off);
    if (lane == 0) g_wboT[(m * 32 + n) * 8 + c] = acc;
}

// ---------------- kG: G[row][col] = Win[row] . WoT2[col]  (warp per element) ----
__global__ void kG(const float* __restrict__ W_in) {
    int w = (blockIdx.x * blockDim.x + threadIdx.x) >> 5;   // 0..65535
    int lane = threadIdx.x & 31;
    int row = w >> 8, col = w & 255;
    const float* a = W_in  + (size_t)row * DD;
    const float* bvec = g_WoT2 + (size_t)col * DD;
    float acc = 0.0f;
#pragma unroll
    for (int i = 0; i < 32; i++)
        acc = fmaf(a[lane + 32 * i], bvec[lane + 32 * i], acc);
#pragma unroll
    for (int off = 16; off > 0; off >>= 1)
        acc += __shfl_xor_sync(0xffffffffu, acc, off);
    if (lane == 0) g_G[row * 256 + col] = acc;

    int t = blockIdx.x * blockDim.x + threadIdx.x;
    if (t < NQ * CD) {
        int m = t >> 3, c = t & 7;
        float s = 0.0f;
        for (int n = 0; n < m; n++) s += g_wboT[(m * 32 + n) * 8 + c];
        g_wboCum[t] = s;
    }
}

// ---------------- gemmZE: ZE0 = mask*(Win_all x z), double-buffered cp.async ----
__global__ void __launch_bounds__(256, 2)
gemmZE(const float* __restrict__ z) {
    __shared__ float As[2][16 * 64];
    __shared__ float Bs[2][16 * 264];
    const int tid  = threadIdx.x;
    const int wm   = tid >> 5;
    const int lane = tid & 31;
    const int bm  = blockIdx.x * 64;
    const int cb0 = blockIdx.y * 256;
    const int b   = cb0 >> 12, t0 = cb0 & 4095;
    const int len = g_len[b];
    const float* zb = z + (size_t)b * DD * TT + t0;

    u64t acc[8][4];
#pragma unroll
    for (int i = 0; i < 8; i++)
#pragma unroll
        for (int p = 0; p < 4; p++) acc[i][p] = 0ull;

    const int arow = tid >> 4, ac4 = tid & 15;
    // prologue: stage tile 0
    {
        cpa16(s2u(&As[0][arow * 64 + ac4 * 4]),
              &g_WinTT[(size_t)arow * 256 + bm + ac4 * 4]);
#pragma unroll
        for (int it = 0; it < 4; it++) {
            int f = it * 256 + tid, brow = f >> 6, bc4 = f & 63;
            cpa16(s2u(&Bs[0][brow * 264 + bc4 * 4]),
                  zb + (size_t)brow * TT + bc4 * 4);
        }
        cpa_commit();
    }

    int buf = 0;
    for (int kk = 0; kk < 1024; kk += 16) {
        cpa_wait_all();
        __syncthreads();
        if (kk + 16 < 1024) {
            int nb = buf ^ 1;
            cpa16(s2u(&As[nb][arow * 64 + ac4 * 4]),
                  &g_WinTT[(size_t)(kk + 16 + arow) * 256 + bm + ac4 * 4]);
#pragma unroll
            for (int it = 0; it < 4; it++) {
                int f = it * 256 + tid, brow = f >> 6, bc4 = f & 63;
                cpa16(s2u(&Bs[nb][brow * 264 + bc4 * 4]),
                      zb + (size_t)(kk + 16 + brow) * TT + bc4 * 4);
            }
            cpa_commit();
        }
#pragma unroll
        for (int k = 0; k < 16; k++) {
            const float* ar = &As[buf][k * 64 + wm * 8];
            float4 a0 = *reinterpret_cast<const float4*>(ar);
            float4 a1 = *reinterpret_cast<const float4*>(ar + 4);
            ulonglong2 bA = *reinterpret_cast<const ulonglong2*>(&Bs[buf][k * 264 + lane * 4]);
            ulonglong2 bB = *reinterpret_cast<const ulonglong2*>(&Bs[buf][k * 264 + 128 + lane * 4]);
            float aa[8] = {a0.x, a0.y, a0.z, a0.w, a1.x, a1.y, a1.z, a1.w};
#pragma unroll
            for (int i = 0; i < 8; i++) {
                u64t ap = pk2(aa[i], aa[i]);
                fma2(acc[i][0], ap, bA.x); fma2(acc[i][1], ap, bA.y);
                fma2(acc[i][2], ap, bB.x); fma2(acc[i][3], ap, bB.y);
            }
        }
        buf ^= 1;
    }
    {
        int tA = t0 + lane * 4, tB = tA + 128;
        float mA0 = (tA     < len) ? 1.0f : 0.0f;
        float mA1 = (tA + 1 < len) ? 1.0f : 0.0f;
        float mA2 = (tA + 2 < len) ? 1.0f : 0.0f;
        float mA3 = (tA + 3 < len) ? 1.0f : 0.0f;
        float mB0 = (tB     < len) ? 1.0f : 0.0f;
        float mB1 = (tB + 1 < len) ? 1.0f : 0.0f;
        float mB2 = (tB + 2 < len) ? 1.0f : 0.0f;
        float mB3 = (tB + 3 < len) ? 1.0f : 0.0f;
#pragma unroll
        for (int i = 0; i < 8; i++) {
            int row = bm + wm * 8 + i;
            float* dst = g_ZE0 + (size_t)row * NCOL + cb0 + lane * 4;
            float2 u0 = upk2(acc[i][0]), u1 = upk2(acc[i][1]);
            float2 u2 = upk2(acc[i][2]), u3 = upk2(acc[i][3]);
            float4 oA = make_float4(u0.x * mA0, u0.y * mA1, u1.x * mA2, u1.y * mA3);
            float4 oB = make_float4(u2.x * mB0, u2.y * mB1, u3.x * mB2, u3.y * mB3);
            *reinterpret_cast<float4*>(dst)       = oA;
            *reinterpret_cast<float4*>(dst + 128) = oB;
        }
    }
}

// ---------------- rvq_scan v4: stripe-split argmax accumulators ----------------
#define SCAN_SMEM_FLOATS (2*8192 + 4096 + 512)
#define SCAN_SMEM_BYTES  (SCAN_SMEM_FLOATS * 4)

__global__ void __launch_bounds__(256, 2)
rvq_scan(const float* __restrict__ b_in, const float* __restrict__ cb,
         float* __restrict__ out, int out_size) {
    extern __shared__ float smem[];
    float*  sCbn = smem;                          // 2 x 8192
    float*  sG   = smem + 2 * 8192;               // 4096
    float2* sArg = (float2*)(smem + 2 * 8192 + 4096);  // [8][32]

    const int tid  = threadIdx.x;
    const int lane = tid & 31;
    const int warp = tid >> 5;
    const int grp  = warp >> 2;
    const int wq   = warp & 3;
    const int col  = blockIdx.x * 64 + grp * 32 + lane;
    const int b = col >> 12, t = col & 4095;
    const float mask = (t < g_len[b]) ? 1.0f : 0.0f;
    const bool write_idx = (out_size >= QOUT_ELEMS + IDX_ELEMS);

    u64t zqh[32];

#pragma unroll
    for (int it = 0; it < 8; it++) {
        int f = it * 256 + tid;
        *reinterpret_cast<float4*>(&sCbn[f * 4]) =
            *reinterpret_cast<const float4*>(&g_cbn[f * 4]);
    }

    for (int c = 0; c < 4; c++) {
        __syncthreads();
#pragma unroll
        for (int it = 0; it < 4; it++) {
            int f = it * 256 + tid, ri = f >> 4, kq = f & 15;
            *reinterpret_cast<float4*>(&sG[ri * 64 + kq * 4]) =
                *reinterpret_cast<const float4*>(&g_G[(c * 64 + ri) * 256 + c * 64 + kq * 4]);
        }
        __syncthreads();

#pragma unroll
        for (int j = 0; j < 8; j++) {
            const int nq = c * 8 + j;
            const float* cbCur = sCbn + (nq & 1) * 8192;

            if (nq < 31) {
                float* cbNxt = sCbn + ((nq + 1) & 1) * 8192;
#pragma unroll
                for (int it = 0; it < 8; it++) {
                    int f = it * 256 + tid;
                    *reinterpret_cast<float4*>(&cbNxt[f * 4]) =
                        *reinterpret_cast<const float4*>(&g_cbn[(size_t)(nq + 1) * 8192 + f * 4]);
                }
            }

            float e[8];
#pragma unroll
            for (int cc = 0; cc < 8; cc++)
                e[cc] = g_ZE0[(size_t)(nq * 8 + cc) * NCOL + col]
                      + __ldg(b_in + nq * 8 + cc)
                      - mask * __ldg(g_wboCum + nq * 8 + cc);
#pragma unroll
            for (int jj = 0; jj < j; jj++)
#pragma unroll
                for (int ci = 0; ci < 8; ci++) {
                    const u64t* gp = reinterpret_cast<const u64t*>(
                        &sG[(j * 8 + ci) * 64 + jj * 8]);
                    u64t a = mul2(gp[0], zqh[jj * 4 + 0]);
                    fma2(a, gp[1], zqh[jj * 4 + 1]);
                    fma2(a, gp[2], zqh[jj * 4 + 2]);
                    fma2(a, gp[3], zqh[jj * 4 + 3]);
                    float2 u = upk2(a);
                    e[ci] -= (u.x + u.y);
                }
            u64t zep[4];
#pragma unroll
            for (int p = 0; p < 4; p++) zep[p] = pk2(e[2 * p], e[2 * p + 1]);

            // argmax: 4 independent stripe accumulators (k mod 4), merged
            // with (value, then smaller-k) -> exact first-max semantics
            float best[4]; int bk[4];
#pragma unroll
            for (int s = 0; s < 4; s++) { best[s] = -3.4e38f; bk[s] = 0; }
            const ulonglong2* cb2 = reinterpret_cast<const ulonglong2*>(cbCur) + wq * 512;
#pragma unroll 2
            for (int kq4 = 0; kq4 < 64; kq4++) {
#pragma unroll
                for (int s = 0; s < 4; s++) {
                    int idx = kq4 * 4 + s;
                    ulonglong2 cA = cb2[idx * 2], cB = cb2[idx * 2 + 1];
                    u64t dp = mul2(zep[0], cA.x);
                    fma2(dp, zep[1], cA.y);
                    fma2(dp, zep[2], cB.x);
                    fma2(dp, zep[3], cB.y);
                    float2 u = upk2(dp);
                    float d = u.x + u.y;
                    if (d > best[s]) { best[s] = d; bk[s] = idx; }
                }
            }
            float bb = best[0]; int bkl = bk[0];
#pragma unroll
            for (int s = 1; s < 4; s++) {
                if (best[s] > bb || (best[s] == bb && bk[s] < bkl)) {
                    bb = best[s]; bkl = bk[s];
                }
            }
            int bkw = wq * 256 + bkl;
            sArg[warp * 32 + lane] = make_float2(bb, __int_as_float(bkw));
            __syncthreads();

            float2 a0 = sArg[(grp * 4 + 0) * 32 + lane];
            float bv = a0.x; int bki = __float_as_int(a0.y);
#pragma unroll
            for (int q = 1; q < 4; q++) {
                float2 aq = sArg[(grp * 4 + q) * 32 + lane];
                if (aq.x > bv) { bv = aq.x; bki = __float_as_int(aq.y); }
            }

            const ulonglong2* pcb = reinterpret_cast<const ulonglong2*>(
                cb + ((size_t)nq * KCB + bki) * CD);
            ulonglong2 qa = __ldg(pcb), qb = __ldg(pcb + 1);
            u64t mm = pk2(mask, mask);
            zqh[j * 4 + 0] = mul2(qa.x, mm);
            zqh[j * 4 + 1] = mul2(qa.y, mm);
            zqh[j * 4 + 2] = mul2(qb.x, mm);
            zqh[j * 4 + 3] = mul2(qb.y, mm);

            if (wq == 0) {
#pragma unroll
                for (int p = 0; p < 4; p++) {
                    float2 u = upk2(zqh[j * 4 + p]);
                    g_ZQ[(size_t)(nq * 8 + 2 * p) * NCOL + col] = u.x;
                    g_ZQ[(size_t)(nq * 8 + 2 * p + 1) * NCOL + col] = u.y;
                }
                if (write_idx)
                    out[QOUT_ELEMS + (size_t)(nq * BB + b) * TT + t] = (float)bki;
            }
            __syncthreads();
        }

        for (int fc = c + 1; fc < 4; fc++) {
            __syncthreads();
#pragma unroll
            for (int it = 0; it < 4; it++) {
                int f = it * 256 + tid, ri = f >> 4, kq = f & 15;
                *reinterpret_cast<float4*>(&sG[ri * 64 + kq * 4]) =
                    *reinterpret_cast<const float4*>(&g_G[(fc * 64 + ri) * 256 + c * 64 + kq * 4]);
            }
            __syncthreads();
#pragma unroll 4
            for (int r16 = 0; r16 < 16; r16++) {
                int r = wq * 16 + r16;
                const u64t* gp = reinterpret_cast<const u64t*>(&sG[r * 64]);
                u64t a = mul2(gp[0], zqh[0]);
#pragma unroll
                for (int q = 1; q < 32; q++) fma2(a, gp[q], zqh[q]);
                float2 u = upk2(a);
                size_t idx = (size_t)(fc * 64 + r) * NCOL + col;
                g_ZE0[idx] -= (u.x + u.y);
            }
        }
    }
}

// ---------------- gemmQ: qout = WoT x ZQ + mask*bsum, double-buffered cp.async ----
__global__ void __launch_bounds__(256, 2)
gemmQ(float* __restrict__ out, int out_size) {
    __shared__ float As[2][16 * 64];
    __shared__ float Bs[2][16 * 264];
    if (out_size < QOUT_ELEMS) return;
    const int tid  = threadIdx.x;
    const int wm   = tid >> 5;
    const int lane = tid & 31;
    const int bm  = blockIdx.x * 64;       // d-tile
    const int cb0 = blockIdx.y * 256;
    const int b   = cb0 >> 12, t0 = cb0 & 4095;
    const int len = g_len[b];

    u64t acc[8][4];
#pragma unroll
    for (int i = 0; i < 8; i++)
#pragma unroll
        for (int p = 0; p < 4; p++) acc[i][p] = 0ull;

    const int arow = tid >> 4, ac4 = tid & 15;
    {
        cpa16(s2u(&As[0][arow * 64 + ac4 * 4]),
              &g_WoT2[(size_t)arow * DD + bm + ac4 * 4]);
#pragma unroll
        for (int it = 0; it < 4; it++) {
            int f = it * 256 + tid, brow = f >> 6, bc4 = f & 63;
            cpa16(s2u(&Bs[0][brow * 264 + bc4 * 4]),
                  g_ZQ + (size_t)brow * NCOL + cb0 + bc4 * 4);
        }
        cpa_commit();
    }

    int buf = 0;
    for (int kk = 0; kk < 256; kk += 16) {
        cpa_wait_all();
        __syncthreads();
        if (kk + 16 < 256) {
            int nb = buf ^ 1;
            cpa16(s2u(&As[nb][arow * 64 + ac4 * 4]),
                  &g_WoT2[(size_t)(kk + 16 + arow) * DD + bm + ac4 * 4]);
#pragma unroll
            for (int it = 0; it < 4; it++) {
                int f = it * 256 + tid, brow = f >> 6, bc4 = f & 63;
                cpa16(s2u(&Bs[nb][brow * 264 + bc4 * 4]),
                      g_ZQ + (size_t)(kk + 16 + brow) * NCOL + cb0 + bc4 * 4);
            }
            cpa_commit();
        }
#pragma unroll
        for (int k = 0; k < 16; k++) {
            const float* ar = &As[buf][k * 64 + wm * 8];
            float4 a0 = *reinterpret_cast<const float4*>(ar);
            float4 a1 = *reinterpret_cast<const float4*>(ar + 4);
            ulonglong2 bA = *reinterpret_cast<const ulonglong2*>(&Bs[buf][k * 264 + lane * 4]);
            ulonglong2 bB = *reinterpret_cast<const ulonglong2*>(&Bs[buf][k * 264 + 128 + lane * 4]);
            float aa[8] = {a0.x, a0.y, a0.z, a0.w, a1.x, a1.y, a1.z, a1.w};
#pragma unroll
            for (int i = 0; i < 8; i++) {
                u64t ap = pk2(aa[i], aa[i]);
                fma2(acc[i][0], ap, bA.x); fma2(acc[i][1], ap, bA.y);
                fma2(acc[i][2], ap, bB.x); fma2(acc[i][3], ap, bB.y);
            }
        }
        buf ^= 1;
    }
    {
        int tA = t0 + lane * 4, tB = tA + 128;
        float mA0 = (tA     < len) ? 1.0f : 0.0f;
        float mA1 = (tA + 1 < len) ? 1.0f : 0.0f;
        float mA2 = (tA + 2 < len) ? 1.0f : 0.0f;
        float mA3 = (tA + 3 < len) ? 1.0f : 0.0f;
        float mB0 = (tB     < len) ? 1.0f : 0.0f;
        float mB1 = (tB + 1 < len) ? 1.0f : 0.0f;
        float mB2 = (tB + 2 < len) ? 1.0f : 0.0f;
        float mB3 = (tB + 3 < len) ? 1.0f : 0.0f;
#pragma unroll
        for (int i = 0; i < 8; i++) {
            int d = bm + wm * 8 + i;
            float bs = __ldg(g_bsum + d);
            float* dst = out + (size_t)b * DD * TT + (size_t)d * TT + t0 + lane * 4;
            float2 u0 = upk2(acc[i][0]), u1 = upk2(acc[i][1]);
            float2 u2 = upk2(acc[i][2]), u3 = upk2(acc[i][3]);
            float4 oA, oB;
            oA.x = (u0.x + mA0 * bs) * mA0;
            oA.y = (u0.y + mA1 * bs) * mA1;
            oA.z = (u1.x + mA2 * bs) * mA2;
            oA.w = (u1.y + mA3 * bs) * mA3;
            oB.x = (u2.x + mB0 * bs) * mB0;
            oB.y = (u2.y + mB1 * bs) * mB1;
            oB.z = (u3.x + mB2 * bs) * mB2;
            oB.w = (u3.y + mB3 * bs) * mB3;
            *reinterpret_cast<float4*>(dst)       = oA;
            *reinterpret_cast<float4*>(dst + 128) = oB;
        }
    }
}

// ---------------------------------------------------------------------------
extern "C" void kernel_launch(void* const* d_in, const int* in_sizes, int n_in,
                              void* d_out, int out_size) {
    const float*     z     = (const float*)d_in[0];
    const long long* len   = (const long long*)d_in[1];
    const float*     W_in  = (const float*)d_in[2];
    const float*     b_in  = (const float*)d_in[3];
    const float*     W_out = (const float*)d_in[4];
    const float*     b_out = (const float*)d_in[5];
    const float*     cbk   = (const float*)d_in[6];
    float* out = (float*)d_out;

    cudaFuncSetAttribute(rvq_scan,
                         cudaFuncAttributeMaxDynamicSharedMemorySize, SCAN_SMEM_BYTES);

    kPre<<<1024, 256>>>(W_in, b_in, W_out, b_out, cbk, len, out, out_size);
    kWbo<<<1024, 256>>>(W_in, b_out);
    kG<<<8192, 256>>>(W_in);
    gemmZE<<<dim3(4, 128), 256>>>(z);
    rvq_scan<<<512, 256, SCAN_SMEM_BYTES>>>(b_in, cbk, out, out_size);
    gemmQ<<<dim3(16, 128), 256>>>(out, out_size);
}

// round 16
// speedup vs baseline: 3.3641x; 1.0102x over previous
#include <cuda_runtime.h>
#include <cstdint>

#define NQ   32
#define KCB  1024
#define CD   8
#define DD   1024
#define TT   4096
#define BB   8
#define NCOL (BB * TT)

#define QOUT_ELEMS (BB * DD * TT)
#define IDX_ELEMS  (NQ * BB * TT)
#define FULL_OUT   (QOUT_ELEMS + IDX_ELEMS + BB)

typedef unsigned long long u64t;

__device__ __forceinline__ u64t pk2(float a, float b) {
    u64t r; asm("mov.b64 %0,{%1,%2};" : "=l"(r) : "f"(a), "f"(b)); return r;
}
__device__ __forceinline__ float2 upk2(u64t v) {
    float2 r; asm("mov.b64 {%0,%1},%2;" : "=f"(r.x), "=f"(r.y) : "l"(v)); return r;
}
__device__ __forceinline__ void fma2(u64t& d, u64t a, u64t b) {
    asm("fma.rn.f32x2 %0,%1,%2,%0;" : "+l"(d) : "l"(a), "l"(b));
}
__device__ __forceinline__ u64t mul2(u64t a, u64t b) {
    u64t r; asm("mul.rn.f32x2 %0,%1,%2;" : "=l"(r) : "l"(a), "l"(b)); return r;
}

// ---- cp.async helpers ----
__device__ __forceinline__ uint32_t s2u(const void* p) {
    uint32_t a;
    asm("{ .reg .u64 t; cvta.to.shared.u64 t, %1; cvt.u32.u64 %0, t; }"
        : "=r"(a) : "l"(p));
    return a;
}
__device__ __forceinline__ void cpa16(uint32_t dst, const void* src) {
    asm volatile("cp.async.ca.shared.global [%0], [%1], 16;" :: "r"(dst), "l"(src));
}
__device__ __forceinline__ void cpa_commit() {
    asm volatile("cp.async.commit_group;");
}
__device__ __forceinline__ void cpa_wait_all() {
    asm volatile("cp.async.wait_group 0;");
}

// scratch (device globals; zero-alloc rule)
__device__ float g_ZE0[256 * NCOL];      // [mc][col]
__device__ float g_ZQ [256 * NCOL];      // [mc][col], masked zq
__device__ float g_G  [256 * 256];
__device__ float g_WinTT[DD * 256];      // [k][m]   A^T for gemmZE + kG
__device__ float g_WoTT [DD * 256];      // [d][mc]  kG operand
__device__ float g_WoT2 [256 * DD];      // [mc][d]  A^T for gemmQ
__device__ float g_cbnI[NQ * KCB * CD];  // pair-interleaved normalized codebooks
__device__ float g_wboT[NQ * NQ * CD];
__device__ float g_wboCum[NQ * CD];
__device__ float g_bsum[DD];
__device__ int   g_len[BB];

// ---------------- kPre: transposes, cbnI, bsum, len ----------------
__global__ void kPre(const float* __restrict__ W_in, const float* __restrict__ b_in,
                     const float* __restrict__ W_out, const float* __restrict__ b_out,
                     const float* __restrict__ cb, const long long* __restrict__ len64,
                     float* __restrict__ out, int out_size) {
    int tid = blockIdx.x * blockDim.x + threadIdx.x;   // 0..262143
    {   // WinTT[k][m] = W_in[m][k]
        int m = tid >> 10, k = tid & 1023;
        g_WinTT[k * 256 + m] = W_in[tid];
    }
    {   // WoTT[d][mc] = W_out[mc>>3][d][mc&7]
        int d = tid >> 8, mc = tid & 255;
        g_WoTT[d * 256 + mc] = W_out[((size_t)(mc >> 3) * DD + d) * CD + (mc & 7)];
    }
    {   // WoT2[mc][d]
        int mc = tid >> 10, d = tid & 1023;
        g_WoT2[tid] = W_out[((size_t)(mc >> 3) * DD + d) * CD + (mc & 7)];
    }
    if (tid < NQ * KCB) {   // normalized codebooks, pair-interleaved layout
        const float* row = cb + (size_t)tid * CD;
        float v[8], n2 = 0.0f;
#pragma unroll
        for (int i = 0; i < 8; i++) { v[i] = row[i]; n2 = fmaf(v[i], v[i], n2); }
        float s = fmaxf(__fsqrt_rn(n2), 1e-12f);
        int h = tid & 1;                     // position within pair
        size_t base = (size_t)(tid >> 1) * 16;
#pragma unroll
        for (int i = 0; i < 8; i++)
            g_cbnI[base + i * 2 + h] = __fdiv_rn(v[i], s);
    }
    if (tid < DD) {
        float s = 0.0f;
        for (int n = 0; n < NQ; n++) s += b_out[(size_t)n * DD + tid];
        g_bsum[tid] = s;
    }
    if (tid == 0) {
        long long tmp[BB]; bool ok = true;
        for (int i = 0; i < BB; i++) { tmp[i] = len64[i]; if (tmp[i] < 0 || tmp[i] > TT) ok = false; }
        if (ok) for (int i = 0; i < BB; i++) g_len[i] = (int)tmp[i];
        else { const int* l = (const int*)len64; for (int i = 0; i < BB; i++) g_len[i] = l[i]; }
        if (out_size >= FULL_OUT)
            for (int i = 0; i < BB; i++) out[QOUT_ELEMS + IDX_ELEMS + i] = (float)g_len[i];
    }
}

// ---------------- kWbo: wbo[m][n][c] = W_in^m[c] . b_out^n  (warp per output) ----
__global__ void kWbo(const float* __restrict__ W_in, const float* __restrict__ b_out) {
    int w = (blockIdx.x * blockDim.x + threadIdx.x) >> 5;   // 0..8191
    int lane = threadIdx.x & 31;
    int m = w >> 8, n = (w >> 3) & 31, c = w & 7;
    const float* wr = W_in + ((size_t)m * CD + c) * DD;
    const float* br = b_out + (size_t)n * DD;
    float acc = 0.0f;
#pragma unroll
    for (int i = 0; i < 32; i++)
        acc = fmaf(wr[lane + 32 * i], br[lane + 32 * i], acc);
#pragma unroll
    for (int off = 16; off > 0; off >>= 1)
        acc += __shfl_xor_sync(0xffffffffu, acc, off);
    if (lane == 0) g_wboT[(m * 32 + n) * 8 + c] = acc;
}

// ---------------- kG: tiled 64x64 G = WinTT^T x WoTT ----------------
__global__ void __launch_bounds__(256)
kG() {
    __shared__ float As[32 * 64];
    __shared__ float Bs[32 * 64];
    const int tid = threadIdx.x, tx = tid & 15, ty = tid >> 4;
    const int r0 = blockIdx.x * 64, c0 = blockIdx.y * 64;
    float acc[4][4];
#pragma unroll
    for (int i = 0; i < 4; i++)
#pragma unroll
        for (int j = 0; j < 4; j++) acc[i][j] = 0.0f;

    for (int kk = 0; kk < 1024; kk += 32) {
#pragma unroll
        for (int it = 0; it < 2; it++) {
            int f = it * 256 + tid, row = f >> 4, c4 = f & 15;
            *reinterpret_cast<float4*>(&As[row * 64 + c4 * 4]) =
                *reinterpret_cast<const float4*>(&g_WinTT[(size_t)(kk + row) * 256 + r0 + c4 * 4]);
            *reinterpret_cast<float4*>(&Bs[row * 64 + c4 * 4]) =
                *reinterpret_cast<const float4*>(&g_WoTT[(size_t)(kk + row) * 256 + c0 + c4 * 4]);
        }
        __syncthreads();
#pragma unroll
        for (int k = 0; k < 32; k++) {
            float4 a = *reinterpret_cast<const float4*>(&As[k * 64 + ty * 4]);
            float4 b = *reinterpret_cast<const float4*>(&Bs[k * 64 + tx * 4]);
            float av[4] = {a.x, a.y, a.z, a.w};
            float bv[4] = {b.x, b.y, b.z, b.w};
#pragma unroll
            for (int i = 0; i < 4; i++)
#pragma unroll
                for (int j = 0; j < 4; j++)
                    acc[i][j] = fmaf(av[i], bv[j], acc[i][j]);
        }
        __syncthreads();
    }
#pragma unroll
    for (int i = 0; i < 4; i++)
#pragma unroll
        for (int j = 0; j < 4; j++)
            g_G[(size_t)(r0 + ty * 4 + i) * 256 + c0 + tx * 4 + j] = acc[i][j];

    // wboCum (block (0,0); g_wboT from kWbo already complete)
    if (blockIdx.x == 0 && blockIdx.y == 0 && tid < NQ * CD) {
        int m = tid >> 3, c = tid & 7;
        float s = 0.0f;
        for (int n = 0; n < m; n++) s += g_wboT[(m * 32 + n) * 8 + c];
        g_wboCum[tid] = s;
    }
}

// ---------------- gemmZE: ZE0 = mask*(Win_all x z), double-buffered cp.async ----
__global__ void __launch_bounds__(256, 2)
gemmZE(const float* __restrict__ z) {
    __shared__ float As[2][16 * 64];
    __shared__ float Bs[2][16 * 264];
    const int tid  = threadIdx.x;
    const int wm   = tid >> 5;
    const int lane = tid & 31;
    const int bm  = blockIdx.x * 64;
    const int cb0 = blockIdx.y * 256;
    const int b   = cb0 >> 12, t0 = cb0 & 4095;
    const int len = g_len[b];
    const float* zb = z + (size_t)b * DD * TT + t0;

    u64t acc[8][4];
#pragma unroll
    for (int i = 0; i < 8; i++)
#pragma unroll
        for (int p = 0; p < 4; p++) acc[i][p] = 0ull;

    const int arow = tid >> 4, ac4 = tid & 15;
    {
        cpa16(s2u(&As[0][arow * 64 + ac4 * 4]),
              &g_WinTT[(size_t)arow * 256 + bm + ac4 * 4]);
#pragma unroll
        for (int it = 0; it < 4; it++) {
            int f = it * 256 + tid, brow = f >> 6, bc4 = f & 63;
            cpa16(s2u(&Bs[0][brow * 264 + bc4 * 4]),
                  zb + (size_t)brow * TT + bc4 * 4);
        }
        cpa_commit();
    }

    int buf = 0;
    for (int kk = 0; kk < 1024; kk += 16) {
        cpa_wait_all();
        __syncthreads();
        if (kk + 16 < 1024) {
            int nb = buf ^ 1;
            cpa16(s2u(&As[nb][arow * 64 + ac4 * 4]),
                  &g_WinTT[(size_t)(kk + 16 + arow) * 256 + bm + ac4 * 4]);
#pragma unroll
            for (int it = 0; it < 4; it++) {
                int f = it * 256 + tid, brow = f >> 6, bc4 = f & 63;
                cpa16(s2u(&Bs[nb][brow * 264 + bc4 * 4]),
                      zb + (size_t)(kk + 16 + brow) * TT + bc4 * 4);
            }
            cpa_commit();
        }
#pragma unroll
        for (int k = 0; k < 16; k++) {
            const float* ar = &As[buf][k * 64 + wm * 8];
            float4 a0 = *reinterpret_cast<const float4*>(ar);
            float4 a1 = *reinterpret_cast<const float4*>(ar + 4);
            ulonglong2 bA = *reinterpret_cast<const ulonglong2*>(&Bs[buf][k * 264 + lane * 4]);
            ulonglong2 bB = *reinterpret_cast<const ulonglong2*>(&Bs[buf][k * 264 + 128 + lane * 4]);
            float aa[8] = {a0.x, a0.y, a0.z, a0.w, a1.x, a1.y, a1.z, a1.w};
#pragma unroll
            for (int i = 0; i < 8; i++) {
                u64t ap = pk2(aa[i], aa[i]);
                fma2(acc[i][0], ap, bA.x); fma2(acc[i][1], ap, bA.y);
                fma2(acc[i][2], ap, bB.x); fma2(acc[i][3], ap, bB.y);
            }
        }
        buf ^= 1;
    }
    {
        int tA = t0 + lane * 4, tB = tA + 128;
        float mA0 = (tA     < len) ? 1.0f : 0.0f;
        float mA1 = (tA + 1 < len) ? 1.0f : 0.0f;
        float mA2 = (tA + 2 < len) ? 1.0f : 0.0f;
        float mA3 = (tA + 3 < len) ? 1.0f : 0.0f;
        float mB0 = (tB     < len) ? 1.0f : 0.0f;
        float mB1 = (tB + 1 < len) ? 1.0f : 0.0f;
        float mB2 = (tB + 2 < len) ? 1.0f : 0.0f;
        float mB3 = (tB + 3 < len) ? 1.0f : 0.0f;
#pragma unroll
        for (int i = 0; i < 8; i++) {
            int row = bm + wm * 8 + i;
            float* dst = g_ZE0 + (size_t)row * NCOL + cb0 + lane * 4;
            float2 u0 = upk2(acc[i][0]), u1 = upk2(acc[i][1]);
            float2 u2 = upk2(acc[i][2]), u3 = upk2(acc[i][3]);
            float4 oA = make_float4(u0.x * mA0, u0.y * mA1, u1.x * mA2, u1.y * mA3);
            float4 oB = make_float4(u2.x * mB0, u2.y * mB1, u3.x * mB2, u3.y * mB3);
            *reinterpret_cast<float4*>(dst)       = oA;
            *reinterpret_cast<float4*>(dst + 128) = oB;
        }
    }
}

// ---------------- rvq_scan v5: 4-step chunks, pair-interleaved argmax ----------------
#define SCAN_SMEM_FLOATS (2*8192 + 1024 + 512)
#define SCAN_SMEM_BYTES  (SCAN_SMEM_FLOATS * 4)

__global__ void __launch_bounds__(256, 2)
rvq_scan(const float* __restrict__ b_in, const float* __restrict__ cb,
         float* __restrict__ out, int out_size) {
    extern __shared__ float smem[];
    float*  sCbn = smem;                          // 2 x 8192 (cbnI)
    float*  sG   = smem + 2 * 8192;               // 1024 (32x32)
    float2* sArg = (float2*)(smem + 2 * 8192 + 1024);  // [8][32]

    const int tid  = threadIdx.x;
    const int lane = tid & 31;
    const int warp = tid >> 5;
    const int grp  = warp >> 2;
    const int wq   = warp & 3;
    const int col  = blockIdx.x * 64 + grp * 32 + lane;
    const int b = col >> 12, t = col & 4095;
    const float mask = (t < g_len[b]) ? 1.0f : 0.0f;
    const bool write_idx = (out_size >= QOUT_ELEMS + IDX_ELEMS);

    u64t zqh[16];   // 4-step chunk history

    // prologue: stage cbnI for nq=0 into buf0
#pragma unroll
    for (int it = 0; it < 8; it++) {
        int f = it * 256 + tid;
        *reinterpret_cast<float4*>(&sCbn[f * 4]) =
            *reinterpret_cast<const float4*>(&g_cbnI[f * 4]);
    }

    for (int c = 0; c < 8; c++) {
        __syncthreads();
        {   // stage in-chunk G block [c][c] (32x32)
            int ri = tid >> 3, kq = tid & 7;
            *reinterpret_cast<float4*>(&sG[ri * 32 + kq * 4]) =
                *reinterpret_cast<const float4*>(&g_G[(c * 32 + ri) * 256 + c * 32 + kq * 4]);
        }
        __syncthreads();

#pragma unroll
        for (int j = 0; j < 4; j++) {
            const int nq = c * 4 + j;
            const float* cbCur = sCbn + (nq & 1) * 8192;

            if (nq < 31) {
                float* cbNxt = sCbn + ((nq + 1) & 1) * 8192;
#pragma unroll
                for (int it = 0; it < 8; it++) {
                    int f = it * 256 + tid;
                    *reinterpret_cast<float4*>(&cbNxt[f * 4]) =
                        *reinterpret_cast<const float4*>(&g_cbnI[(size_t)(nq + 1) * 8192 + f * 4]);
                }
            }

            // build e for this lane's column
            float e[8];
#pragma unroll
            for (int cc = 0; cc < 8; cc++)
                e[cc] = g_ZE0[(size_t)(nq * 8 + cc) * NCOL + col]
                      + __ldg(b_in + nq * 8 + cc)
                      - mask * __ldg(g_wboCum + nq * 8 + cc);
#pragma unroll
            for (int jj = 0; jj < j; jj++)
#pragma unroll
                for (int ci = 0; ci < 8; ci++) {
                    const u64t* gp = reinterpret_cast<const u64t*>(
                        &sG[(j * 8 + ci) * 32 + jj * 8]);
                    u64t a = mul2(gp[0], zqh[jj * 4 + 0]);
                    fma2(a, gp[1], zqh[jj * 4 + 1]);
                    fma2(a, gp[2], zqh[jj * 4 + 2]);
                    fma2(a, gp[3], zqh[jj * 4 + 3]);
                    float2 u = upk2(a);
                    e[ci] -= (u.x + u.y);
                }
            u64t ep[8];
#pragma unroll
            for (int cc = 0; cc < 8; cc++) ep[cc] = pk2(e[cc], e[cc]);

            // argmax via pair-interleaved codebook; 4 stripe accumulators
            float best0 = -3.4e38f, best1 = -3.4e38f, best2 = -3.4e38f, best3 = -3.4e38f;
            int   bk0 = 0, bk1 = 0, bk2 = 0, bk3 = 0;
            const ulonglong2* cbI = reinterpret_cast<const ulonglong2*>(cbCur);
#pragma unroll 2
            for (int i2 = 0; i2 < 64; i2++) {
                int pA = wq * 128 + i2, pB = pA + 64;
                ulonglong2 a0 = cbI[pA * 4 + 0], a1 = cbI[pA * 4 + 1];
                ulonglong2 a2 = cbI[pA * 4 + 2], a3 = cbI[pA * 4 + 3];
                u64t dA = mul2(ep[0], a0.x);
                fma2(dA, ep[1], a0.y); fma2(dA, ep[2], a1.x); fma2(dA, ep[3], a1.y);
                fma2(dA, ep[4], a2.x); fma2(dA, ep[5], a2.y); fma2(dA, ep[6], a3.x);
                fma2(dA, ep[7], a3.y);
                ulonglong2 b0 = cbI[pB * 4 + 0], b1 = cbI[pB * 4 + 1];
                ulonglong2 b2 = cbI[pB * 4 + 2], b3 = cbI[pB * 4 + 3];
                u64t dB = mul2(ep[0], b0.x);
                fma2(dB, ep[1], b0.y); fma2(dB, ep[2], b1.x); fma2(dB, ep[3], b1.y);
                fma2(dB, ep[4], b2.x); fma2(dB, ep[5], b2.y); fma2(dB, ep[6], b3.x);
                fma2(dB, ep[7], b3.y);
                float2 uA = upk2(dA), uB = upk2(dB);
                int kA = 2 * pA, kB = 2 * pB;
                if (uA.x > best0) { best0 = uA.x; bk0 = kA; }
                if (uA.y > best1) { best1 = uA.y; bk1 = kA + 1; }
                if (uB.x > best2) { best2 = uB.x; bk2 = kB; }
                if (uB.y > best3) { best3 = uB.y; bk3 = kB + 1; }
            }
            // merge stripes: value first, then smaller k (exact first-max)
            float bb = best0; int bkl = bk0;
            if (best1 > bb || (best1 == bb && bk1 < bkl)) { bb = best1; bkl = bk1; }
            if (best2 > bb || (best2 == bb && bk2 < bkl)) { bb = best2; bkl = bk2; }
            if (best3 > bb || (best3 == bb && bk3 < bkl)) { bb = best3; bkl = bk3; }
            sArg[warp * 32 + lane] = make_float2(bb, __int_as_float(bkl));
            __syncthreads();   // sArg visible + cbNxt staged

            // combine quarters in ascending-k order (first-max semantics)
            float2 a0c = sArg[(grp * 4 + 0) * 32 + lane];
            float bv = a0c.x; int bki = __float_as_int(a0c.y);
#pragma unroll
            for (int q = 1; q < 4; q++) {
                float2 aq = sArg[(grp * 4 + q) * 32 + lane];
                if (aq.x > bv) { bv = aq.x; bki = __float_as_int(aq.y); }
            }

            // gather raw codeword, mask, record history
            const ulonglong2* pcb = reinterpret_cast<const ulonglong2*>(
                cb + ((size_t)nq * KCB + bki) * CD);
            ulonglong2 qa = __ldg(pcb), qb = __ldg(pcb + 1);
            u64t mm = pk2(mask, mask);
            zqh[j * 4 + 0] = mul2(qa.x, mm);
            zqh[j * 4 + 1] = mul2(qa.y, mm);
            zqh[j * 4 + 2] = mul2(qb.x, mm);
            zqh[j * 4 + 3] = mul2(qb.y, mm);

            if (wq == 0) {
#pragma unroll
                for (int p = 0; p < 4; p++) {
                    float2 u = upk2(zqh[j * 4 + p]);
                    g_ZQ[(size_t)(nq * 8 + 2 * p) * NCOL + col] = u.x;
                    g_ZQ[(size_t)(nq * 8 + 2 * p + 1) * NCOL + col] = u.y;
                }
                if (write_idx)
                    out[QOUT_ELEMS + (size_t)(nq * BB + b) * TT + t] = (float)bki;
            }
            __syncthreads();   // sArg consumed before next step's writes
        }

        // fold chunk into future ZE0 rows (32 rows split across 4 warps)
        for (int fc = c + 1; fc < 8; fc++) {
            __syncthreads();
            {
                int ri = tid >> 3, kq = tid & 7;
                *reinterpret_cast<float4*>(&sG[ri * 32 + kq * 4]) =
                    *reinterpret_cast<const float4*>(&g_G[(fc * 32 + ri) * 256 + c * 32 + kq * 4]);
            }
            __syncthreads();
#pragma unroll
            for (int r8 = 0; r8 < 8; r8++) {
                int r = wq * 8 + r8;
                const u64t* gp = reinterpret_cast<const u64t*>(&sG[r * 32]);
                u64t a = mul2(gp[0], zqh[0]);
#pragma unroll
                for (int q = 1; q < 16; q++) fma2(a, gp[q], zqh[q]);
                float2 u = upk2(a);
                size_t idx = (size_t)(fc * 32 + r) * NCOL + col;
                g_ZE0[idx] -= (u.x + u.y);
            }
        }
    }
}

// ---------------- gemmQ: qout = WoT x ZQ + mask*bsum, double-buffered cp.async ----
__global__ void __launch_bounds__(256, 2)
gemmQ(float* __restrict__ out, int out_size) {
    __shared__ float As[2][16 * 64];
    __shared__ float Bs[2][16 * 264];
    if (out_size < QOUT_ELEMS) return;
    const int tid  = threadIdx.x;
    const int wm   = tid >> 5;
    const int lane = tid & 31;
    const int bm  = blockIdx.x * 64;       // d-tile
    const int cb0 = blockIdx.y * 256;
    const int b   = cb0 >> 12, t0 = cb0 & 4095;
    const int len = g_len[b];

    u64t acc[8][4];
#pragma unroll
    for (int i = 0; i < 8; i++)
#pragma unroll
        for (int p = 0; p < 4; p++) acc[i][p] = 0ull;

    const int arow = tid >> 4, ac4 = tid & 15;
    {
        cpa16(s2u(&As[0][arow * 64 + ac4 * 4]),
              &g_WoT2[(size_t)arow * DD + bm + ac4 * 4]);
#pragma unroll
        for (int it = 0; it < 4; it++) {
            int f = it * 256 + tid, brow = f >> 6, bc4 = f & 63;
            cpa16(s2u(&Bs[0][brow * 264 + bc4 * 4]),
                  g_ZQ + (size_t)brow * NCOL + cb0 + bc4 * 4);
        }
        cpa_commit();
    }

    int buf = 0;
    for (int kk = 0; kk < 256; kk += 16) {
        cpa_wait_all();
        __syncthreads();
        if (kk + 16 < 256) {
            int nb = buf ^ 1;
            cpa16(s2u(&As[nb][arow * 64 + ac4 * 4]),
                  &g_WoT2[(size_t)(kk + 16 + arow) * DD + bm + ac4 * 4]);
#pragma unroll
            for (int it = 0; it < 4; it++) {
                int f = it * 256 + tid, brow = f >> 6, bc4 = f & 63;
                cpa16(s2u(&Bs[nb][brow * 264 + bc4 * 4]),
                      g_ZQ + (size_t)(kk + 16 + brow) * NCOL + cb0 + bc4 * 4);
            }
            cpa_commit();
        }
#pragma unroll
        for (int k = 0; k < 16; k++) {
            const float* ar = &As[buf][k * 64 + wm * 8];
            float4 a0 = *reinterpret_cast<const float4*>(ar);
            float4 a1 = *reinterpret_cast<const float4*>(ar + 4);
            ulonglong2 bA = *reinterpret_cast<const ulonglong2*>(&Bs[buf][k * 264 + lane * 4]);
            ulonglong2 bB = *reinterpret_cast<const ulonglong2*>(&Bs[buf][k * 264 + 128 + lane * 4]);
            float aa[8] = {a0.x, a0.y, a0.z, a0.w, a1.x, a1.y, a1.z, a1.w};
#pragma unroll
            for (int i = 0; i < 8; i++) {
                u64t ap = pk2(aa[i], aa[i]);
                fma2(acc[i][0], ap, bA.x); fma2(acc[i][1], ap, bA.y);
                fma2(acc[i][2], ap, bB.x); fma2(acc[i][3], ap, bB.y);
            }
        }
        buf ^= 1;
    }
    {
        int tA = t0 + lane * 4, tB = tA + 128;
        float mA0 = (tA     < len) ? 1.0f : 0.0f;
        float mA1 = (tA + 1 < len) ? 1.0f : 0.0f;
        float mA2 = (tA + 2 < len) ? 1.0f : 0.0f;
        float mA3 = (tA + 3 < len) ? 1.0f : 0.0f;
        float mB0 = (tB     < len) ? 1.0f : 0.0f;
        float mB1 = (tB + 1 < len) ? 1.0f : 0.0f;
        float mB2 = (tB + 2 < len) ? 1.0f : 0.0f;
        float mB3 = (tB + 3 < len) ? 1.0f : 0.0f;
#pragma unroll
        for (int i = 0; i < 8; i++) {
            int d = bm + wm * 8 + i;
            float bs = __ldg(g_bsum + d);
            float* dst = out + (size_t)b * DD * TT + (size_t)d * TT + t0 + lane * 4;
            float2 u0 = upk2(acc[i][0]), u1 = upk2(acc[i][1]);
            float2 u2 = upk2(acc[i][2]), u3 = upk2(acc[i][3]);
            float4 oA, oB;
            oA.x = (u0.x + mA0 * bs) * mA0;
            oA.y = (u0.y + mA1 * bs) * mA1;
            oA.z = (u1.x + mA2 * bs) * mA2;
            oA.w = (u1.y + mA3 * bs) * mA3;
            oB.x = (u2.x + mB0 * bs) * mB0;
            oB.y = (u2.y + mB1 * bs) * mB1;
            oB.z = (u3.x + mB2 * bs) * mB2;
            oB.w = (u3.y + mB3 * bs) * mB3;
            *reinterpret_cast<float4*>(dst)       = oA;
            *reinterpret_cast<float4*>(dst + 128) = oB;
        }
    }
}

// ---------------------------------------------------------------------------
extern "C" void kernel_launch(void* const* d_in, const int* in_sizes, int n_in,
                              void* d_out, int out_size) {
    const float*     z     = (const float*)d_in[0];
    const long long* len   = (const long long*)d_in[1];
    const float*     W_in  = (const float*)d_in[2];
    const float*     b_in  = (const float*)d_in[3];
    const float*     W_out = (const float*)d_in[4];
    const float*     b_out = (const float*)d_in[5];
    const float*     cbk   = (const float*)d_in[6];
    float* out = (float*)d_out;

    cudaFuncSetAttribute(rvq_scan,
                         cudaFuncAttributeMaxDynamicSharedMemorySize, SCAN_SMEM_BYTES);

    kPre<<<1024, 256>>>(W_in, b_in, W_out, b_out, cbk, len, out, out_size);
    kWbo<<<1024, 256>>>(W_in, b_out);
    kG<<<dim3(4, 4), 256>>>();
    gemmZE<<<dim3(4, 128), 256>>>(z);
    rvq_scan<<<512, 256, SCAN_SMEM_BYTES>>>(b_in, cbk, out, out_size);
    gemmQ<<<dim3(16, 128), 256>>>(out, out_size);
}

// round 17
// speedup vs baseline: 3.3858x; 1.0065x over previous
#include <cuda_runtime.h>
#include <cstdint>

#define NQ   32
#define KCB  1024
#define CD   8
#define DD   1024
#define TT   4096
#define BB   8
#define NCOL (BB * TT)

#define QOUT_ELEMS (BB * DD * TT)
#define IDX_ELEMS  (NQ * BB * TT)
#define FULL_OUT   (QOUT_ELEMS + IDX_ELEMS + BB)

typedef unsigned long long u64t;

__device__ __forceinline__ u64t pk2(float a, float b) {
    u64t r; asm("mov.b64 %0,{%1,%2};" : "=l"(r) : "f"(a), "f"(b)); return r;
}
__device__ __forceinline__ float2 upk2(u64t v) {
    float2 r; asm("mov.b64 {%0,%1},%2;" : "=f"(r.x), "=f"(r.y) : "l"(v)); return r;
}
__device__ __forceinline__ void fma2(u64t& d, u64t a, u64t b) {
    asm("fma.rn.f32x2 %0,%1,%2,%0;" : "+l"(d) : "l"(a), "l"(b));
}
__device__ __forceinline__ u64t mul2(u64t a, u64t b) {
    u64t r; asm("mul.rn.f32x2 %0,%1,%2;" : "=l"(r) : "l"(a), "l"(b)); return r;
}

// ---- cp.async helpers ----
__device__ __forceinline__ uint32_t s2u(const void* p) {
    uint32_t a;
    asm("{ .reg .u64 t; cvta.to.shared.u64 t, %1; cvt.u32.u64 %0, t; }"
        : "=r"(a) : "l"(p));
    return a;
}
__device__ __forceinline__ void cpa16(uint32_t dst, const void* src) {
    asm volatile("cp.async.ca.shared.global [%0], [%1], 16;" :: "r"(dst), "l"(src));
}
__device__ __forceinline__ void cpa_commit() {
    asm volatile("cp.async.commit_group;");
}
__device__ __forceinline__ void cpa_wait_all() {
    asm volatile("cp.async.wait_group 0;");
}

// scratch (device globals; zero-alloc rule)
__device__ float g_ZE0[256 * NCOL];      // [mc][col]
__device__ float g_ZQ [256 * NCOL];      // [mc][col], masked zq
__device__ float g_G  [256 * 256];
__device__ float g_WinTT[DD * 256];      // [k][m]   A^T for gemmZE + kG
__device__ float g_WoTT [DD * 256];      // [d][mc]  kG operand
__device__ float g_WoT2 [256 * DD];      // [mc][d]  A^T for gemmQ
__device__ float g_cbnI[NQ * KCB * CD];  // pair-interleaved normalized codebooks
__device__ float g_wboT[NQ * NQ * CD];
__device__ float g_wboCum[NQ * CD];
__device__ float g_bsum[DD];
__device__ int   g_len[BB];

// ---------------- kPre ----------------
__global__ void kPre(const float* __restrict__ W_in, const float* __restrict__ b_in,
                     const float* __restrict__ W_out, const float* __restrict__ b_out,
                     const float* __restrict__ cb, const long long* __restrict__ len64,
                     float* __restrict__ out, int out_size) {
    int tid = blockIdx.x * blockDim.x + threadIdx.x;   // 0..262143
    {   // WinTT[k][m] = W_in[m][k]
        int m = tid >> 10, k = tid & 1023;
        g_WinTT[k * 256 + m] = W_in[tid];
    }
    {   // WoTT[d][mc] = W_out[mc>>3][d][mc&7]
        int d = tid >> 8, mc = tid & 255;
        g_WoTT[d * 256 + mc] = W_out[((size_t)(mc >> 3) * DD + d) * CD + (mc & 7)];
    }
    {   // WoT2[mc][d]
        int mc = tid >> 10, d = tid & 1023;
        g_WoT2[tid] = W_out[((size_t)(mc >> 3) * DD + d) * CD + (mc & 7)];
    }
    if (tid < NQ * KCB) {   // normalized codebooks, pair-interleaved layout
        const float* row = cb + (size_t)tid * CD;
        float v[8], n2 = 0.0f;
#pragma unroll
        for (int i = 0; i < 8; i++) { v[i] = row[i]; n2 = fmaf(v[i], v[i], n2); }
        float s = fmaxf(__fsqrt_rn(n2), 1e-12f);
        int h = tid & 1;
        size_t base = (size_t)(tid >> 1) * 16;
#pragma unroll
        for (int i = 0; i < 8; i++)
            g_cbnI[base + i * 2 + h] = __fdiv_rn(v[i], s);
    }
    if (tid < DD) {
        float s = 0.0f;
        for (int n = 0; n < NQ; n++) s += b_out[(size_t)n * DD + tid];
        g_bsum[tid] = s;
    }
    if (tid == 0) {
        long long tmp[BB]; bool ok = true;
        for (int i = 0; i < BB; i++) { tmp[i] = len64[i]; if (tmp[i] < 0 || tmp[i] > TT) ok = false; }
        if (ok) for (int i = 0; i < BB; i++) g_len[i] = (int)tmp[i];
        else { const int* l = (const int*)len64; for (int i = 0; i < BB; i++) g_len[i] = l[i]; }
        if (out_size >= FULL_OUT)
            for (int i = 0; i < BB; i++) out[QOUT_ELEMS + IDX_ELEMS + i] = (float)g_len[i];
    }
}

// ---------------- kWbo ----------------
__global__ void kWbo(const float* __restrict__ W_in, const float* __restrict__ b_out) {
    int w = (blockIdx.x * blockDim.x + threadIdx.x) >> 5;   // 0..8191
    int lane = threadIdx.x & 31;
    int m = w >> 8, n = (w >> 3) & 31, c = w & 7;
    const float* wr = W_in + ((size_t)m * CD + c) * DD;
    const float* br = b_out + (size_t)n * DD;
    float acc = 0.0f;
#pragma unroll
    for (int i = 0; i < 32; i++)
        acc = fmaf(wr[lane + 32 * i], br[lane + 32 * i], acc);
#pragma unroll
    for (int off = 16; off > 0; off >>= 1)
        acc += __shfl_xor_sync(0xffffffffu, acc, off);
    if (lane == 0) g_wboT[(m * 32 + n) * 8 + c] = acc;
}

// ---------------- kG: tiled 64x64 G = WinTT^T x WoTT ----------------
__global__ void __launch_bounds__(256)
kG() {
    __shared__ float As[32 * 64];
    __shared__ float Bs[32 * 64];
    const int tid = threadIdx.x, tx = tid & 15, ty = tid >> 4;
    const int r0 = blockIdx.x * 64, c0 = blockIdx.y * 64;
    float acc[4][4];
#pragma unroll
    for (int i = 0; i < 4; i++)
#pragma unroll
        for (int j = 0; j < 4; j++) acc[i][j] = 0.0f;

    for (int kk = 0; kk < 1024; kk += 32) {
#pragma unroll
        for (int it = 0; it < 2; it++) {
            int f = it * 256 + tid, row = f >> 4, c4 = f & 15;
            *reinterpret_cast<float4*>(&As[row * 64 + c4 * 4]) =
                *reinterpret_cast<const float4*>(&g_WinTT[(size_t)(kk + row) * 256 + r0 + c4 * 4]);
            *reinterpret_cast<float4*>(&Bs[row * 64 + c4 * 4]) =
                *reinterpret_cast<const float4*>(&g_WoTT[(size_t)(kk + row) * 256 + c0 + c4 * 4]);
        }
        __syncthreads();
#pragma unroll
        for (int k = 0; k < 32; k++) {
            float4 a = *reinterpret_cast<const float4*>(&As[k * 64 + ty * 4]);
            float4 b = *reinterpret_cast<const float4*>(&Bs[k * 64 + tx * 4]);
            float av[4] = {a.x, a.y, a.z, a.w};
            float bv[4] = {b.x, b.y, b.z, b.w};
#pragma unroll
            for (int i = 0; i < 4; i++)
#pragma unroll
                for (int j = 0; j < 4; j++)
                    acc[i][j] = fmaf(av[i], bv[j], acc[i][j]);
        }
        __syncthreads();
    }
#pragma unroll
    for (int i = 0; i < 4; i++)
#pragma unroll
        for (int j = 0; j < 4; j++)
            g_G[(size_t)(r0 + ty * 4 + i) * 256 + c0 + tx * 4 + j] = acc[i][j];

    if (blockIdx.x == 0 && blockIdx.y == 0 && tid < NQ * CD) {
        int m = tid >> 3, c = tid & 7;
        float s = 0.0f;
        for (int n = 0; n < m; n++) s += g_wboT[(m * 32 + n) * 8 + c];
        g_wboCum[tid] = s;
    }
}

// ---------------- gemmZE: ZE0 = mask*(Win_all x z), k-tile 32, cp.async ----------------
#define GEMM_SMEM_FLOATS (2*32*64 + 2*32*264)
#define GEMM_SMEM_BYTES  (GEMM_SMEM_FLOATS * 4)       // 83,968 B

__global__ void __launch_bounds__(256, 2)
gemmZE(const float* __restrict__ z) {
    extern __shared__ float gsm[];
    float* As = gsm;               // [2][32*64]
    float* Bs = gsm + 2 * 2048;    // [2][32*264]
    const int tid  = threadIdx.x;
    const int wm   = tid >> 5;
    const int lane = tid & 31;
    const int bm  = blockIdx.x * 64;
    const int cb0 = blockIdx.y * 256;
    const int b   = cb0 >> 12, t0 = cb0 & 4095;
    const int len = g_len[b];
    const float* zb = z + (size_t)b * DD * TT + t0;

    u64t acc[8][4];
#pragma unroll
    for (int i = 0; i < 8; i++)
#pragma unroll
        for (int p = 0; p < 4; p++) acc[i][p] = 0ull;

    {   // prologue: tile 0
#pragma unroll
        for (int it = 0; it < 2; it++) {
            int f = it * 256 + tid, row = f >> 4, c4 = f & 15;
            cpa16(s2u(&As[row * 64 + c4 * 4]),
                  &g_WinTT[(size_t)row * 256 + bm + c4 * 4]);
        }
#pragma unroll
        for (int it = 0; it < 8; it++) {
            int f = it * 256 + tid, brow = f >> 6, bc4 = f & 63;
            cpa16(s2u(&Bs[brow * 264 + bc4 * 4]),
                  zb + (size_t)brow * TT + bc4 * 4);
        }
        cpa_commit();
    }

    int buf = 0;
    for (int kk = 0; kk < 1024; kk += 32) {
        cpa_wait_all();
        __syncthreads();
        if (kk + 32 < 1024) {
            int nb = buf ^ 1;
#pragma unroll
            for (int it = 0; it < 2; it++) {
                int f = it * 256 + tid, row = f >> 4, c4 = f & 15;
                cpa16(s2u(&As[nb * 2048 + row * 64 + c4 * 4]),
                      &g_WinTT[(size_t)(kk + 32 + row) * 256 + bm + c4 * 4]);
            }
#pragma unroll
            for (int it = 0; it < 8; it++) {
                int f = it * 256 + tid, brow = f >> 6, bc4 = f & 63;
                cpa16(s2u(&Bs[nb * 8448 + brow * 264 + bc4 * 4]),
                      zb + (size_t)(kk + 32 + brow) * TT + bc4 * 4);
            }
            cpa_commit();
        }
        const float* Ab = As + buf * 2048;
        const float* Bb = Bs + buf * 8448;
#pragma unroll
        for (int k = 0; k < 32; k++) {
            const float* ar = &Ab[k * 64 + wm * 8];
            float4 a0 = *reinterpret_cast<const float4*>(ar);
            float4 a1 = *reinterpret_cast<const float4*>(ar + 4);
            ulonglong2 bA = *reinterpret_cast<const ulonglong2*>(&Bb[k * 264 + lane * 4]);
            ulonglong2 bB = *reinterpret_cast<const ulonglong2*>(&Bb[k * 264 + 128 + lane * 4]);
            float aa[8] = {a0.x, a0.y, a0.z, a0.w, a1.x, a1.y, a1.z, a1.w};
#pragma unroll
            for (int i = 0; i < 8; i++) {
                u64t ap = pk2(aa[i], aa[i]);
                fma2(acc[i][0], ap, bA.x); fma2(acc[i][1], ap, bA.y);
                fma2(acc[i][2], ap, bB.x); fma2(acc[i][3], ap, bB.y);
            }
        }
        buf ^= 1;
    }
    {
        int tA = t0 + lane * 4, tB = tA + 128;
        float mA0 = (tA     < len) ? 1.0f : 0.0f;
        float mA1 = (tA + 1 < len) ? 1.0f : 0.0f;
        float mA2 = (tA + 2 < len) ? 1.0f : 0.0f;
        float mA3 = (tA + 3 < len) ? 1.0f : 0.0f;
        float mB0 = (tB     < len) ? 1.0f : 0.0f;
        float mB1 = (tB + 1 < len) ? 1.0f : 0.0f;
        float mB2 = (tB + 2 < len) ? 1.0f : 0.0f;
        float mB3 = (tB + 3 < len) ? 1.0f : 0.0f;
#pragma unroll
        for (int i = 0; i < 8; i++) {
            int row = bm + wm * 8 + i;
            float* dst = g_ZE0 + (size_t)row * NCOL + cb0 + lane * 4;
            float2 u0 = upk2(acc[i][0]), u1 = upk2(acc[i][1]);
            float2 u2 = upk2(acc[i][2]), u3 = upk2(acc[i][3]);
            float4 oA = make_float4(u0.x * mA0, u0.y * mA1, u1.x * mA2, u1.y * mA3);
            float4 oB = make_float4(u2.x * mB0, u2.y * mB1, u3.x * mB2, u3.y * mB3);
            *reinterpret_cast<float4*>(dst)       = oA;
            *reinterpret_cast<float4*>(dst + 128) = oB;
        }
    }
}

// ---------------- rvq_scan v6: 1 barrier/step, per-chunk G strip, no fold barriers ----
#define SCAN_SMEM_FLOATS (2*8192 + 8192 + 1024)
#define SCAN_SMEM_BYTES  (SCAN_SMEM_FLOATS * 4)       // 102,400 B

__global__ void __launch_bounds__(256, 2)
rvq_scan(const float* __restrict__ b_in, const float* __restrict__ cb,
         float* __restrict__ out, int out_size) {
    extern __shared__ float smem[];
    float*  sCbn = smem;                              // 2 x 8192 (cbnI)
    float*  sGAll = smem + 2 * 8192;                  // 256 x 32 (G column strip)
    float2* sArg = (float2*)(smem + 2 * 8192 + 8192); // [2][256]

    const int tid  = threadIdx.x;
    const int lane = tid & 31;
    const int warp = tid >> 5;
    const int grp  = warp >> 2;
    const int wq   = warp & 3;
    const int col  = blockIdx.x * 64 + grp * 32 + lane;
    const int b = col >> 12, t = col & 4095;
    const float mask = (t < g_len[b]) ? 1.0f : 0.0f;
    const bool write_idx = (out_size >= QOUT_ELEMS + IDX_ELEMS);

    u64t zqh[16];   // 4-step chunk history

    // prologue: stage cbnI for nq=0 into buf0
#pragma unroll
    for (int it = 0; it < 8; it++) {
        int f = it * 256 + tid;
        *reinterpret_cast<float4*>(&sCbn[f * 4]) =
            *reinterpret_cast<const float4*>(&g_cbnI[f * 4]);
    }

    for (int c = 0; c < 8; c++) {
        __syncthreads();   // fences prior folds / sArg reads / prologue staging
        // stage the full 256x32 G column strip for this chunk
#pragma unroll
        for (int it = 0; it < 8; it++) {
            int f = it * 256 + tid;           // float4 index, 0..2047
            int row = f >> 3, q = f & 7;
            *reinterpret_cast<float4*>(&sGAll[row * 32 + q * 4]) =
                *reinterpret_cast<const float4*>(&g_G[(size_t)row * 256 + c * 32 + q * 4]);
        }
        __syncthreads();

#pragma unroll
        for (int j = 0; j < 4; j++) {
            const int nq = c * 4 + j;
            const float* cbCur = sCbn + (nq & 1) * 8192;

            if (nq < 31) {
                float* cbNxt = sCbn + ((nq + 1) & 1) * 8192;
#pragma unroll
                for (int it = 0; it < 8; it++) {
                    int f = it * 256 + tid;
                    *reinterpret_cast<float4*>(&cbNxt[f * 4]) =
                        *reinterpret_cast<const float4*>(&g_cbnI[(size_t)(nq + 1) * 8192 + f * 4]);
                }
            }

            // build e for this lane's column
            float e[8];
#pragma unroll
            for (int cc = 0; cc < 8; cc++)
                e[cc] = g_ZE0[(size_t)(nq * 8 + cc) * NCOL + col]
                      + __ldg(b_in + nq * 8 + cc)
                      - mask * __ldg(g_wboCum + nq * 8 + cc);
#pragma unroll
            for (int jj = 0; jj < j; jj++)
#pragma unroll
                for (int ci = 0; ci < 8; ci++) {
                    const u64t* gp = reinterpret_cast<const u64t*>(
                        &sGAll[(c * 32 + j * 8 + ci) * 32 + jj * 8]);
                    u64t a = mul2(gp[0], zqh[jj * 4 + 0]);
                    fma2(a, gp[1], zqh[jj * 4 + 1]);
                    fma2(a, gp[2], zqh[jj * 4 + 2]);
                    fma2(a, gp[3], zqh[jj * 4 + 3]);
                    float2 u = upk2(a);
                    e[ci] -= (u.x + u.y);
                }
            u64t ep[8];
#pragma unroll
            for (int cc = 0; cc < 8; cc++) ep[cc] = pk2(e[cc], e[cc]);

            // argmax via pair-interleaved codebook; 4 stripe accumulators
            float best0 = -3.4e38f, best1 = -3.4e38f, best2 = -3.4e38f, best3 = -3.4e38f;
            int   bk0 = 0, bk1 = 0, bk2 = 0, bk3 = 0;
            const ulonglong2* cbI = reinterpret_cast<const ulonglong2*>(cbCur);
#pragma unroll 2
            for (int i2 = 0; i2 < 64; i2++) {
                int pA = wq * 128 + i2, pB = pA + 64;
                ulonglong2 a0 = cbI[pA * 4 + 0], a1 = cbI[pA * 4 + 1];
                ulonglong2 a2 = cbI[pA * 4 + 2], a3 = cbI[pA * 4 + 3];
                u64t dA = mul2(ep[0], a0.x);
                fma2(dA, ep[1], a0.y); fma2(dA, ep[2], a1.x); fma2(dA, ep[3], a1.y);
                fma2(dA, ep[4], a2.x); fma2(dA, ep[5], a2.y); fma2(dA, ep[6], a3.x);
                fma2(dA, ep[7], a3.y);
                ulonglong2 b0 = cbI[pB * 4 + 0], b1 = cbI[pB * 4 + 1];
                ulonglong2 b2 = cbI[pB * 4 + 2], b3 = cbI[pB * 4 + 3];
                u64t dB = mul2(ep[0], b0.x);
                fma2(dB, ep[1], b0.y); fma2(dB, ep[2], b1.x); fma2(dB, ep[3], b1.y);
                fma2(dB, ep[4], b2.x); fma2(dB, ep[5], b2.y); fma2(dB, ep[6], b3.x);
                fma2(dB, ep[7], b3.y);
                float2 uA = upk2(dA), uB = upk2(dB);
                int kA = 2 * pA, kB = 2 * pB;
                if (uA.x > best0) { best0 = uA.x; bk0 = kA; }
                if (uA.y > best1) { best1 = uA.y; bk1 = kA + 1; }
                if (uB.x > best2) { best2 = uB.x; bk2 = kB; }
                if (uB.y > best3) { best3 = uB.y; bk3 = kB + 1; }
            }
            // merge stripes: value first, then smaller k (exact first-max)
            float bb = best0; int bkl = bk0;
            if (best1 > bb || (best1 == bb && bk1 < bkl)) { bb = best1; bkl = bk1; }
            if (best2 > bb || (best2 == bb && bk2 < bkl)) { bb = best2; bkl = bk2; }
            if (best3 > bb || (best3 == bb && bk3 < bkl)) { bb = best3; bkl = bk3; }

            float2* argBuf = sArg + (size_t)(nq & 1) * 256;
            argBuf[warp * 32 + lane] = make_float2(bb, __int_as_float(bkl));
            __syncthreads();   // sArg visible + cbNxt staged (single barrier per step)

            // combine quarters in ascending-k order (first-max semantics)
            float2 a0c = argBuf[(grp * 4 + 0) * 32 + lane];
            float bv = a0c.x; int bki = __float_as_int(a0c.y);
#pragma unroll
            for (int q = 1; q < 4; q++) {
                float2 aq = argBuf[(grp * 4 + q) * 32 + lane];
                if (aq.x > bv) { bv = aq.x; bki = __float_as_int(aq.y); }
            }

            // gather raw codeword, mask, record history
            const ulonglong2* pcb = reinterpret_cast<const ulonglong2*>(
                cb + ((size_t)nq * KCB + bki) * CD);
            ulonglong2 qa = __ldg(pcb), qb = __ldg(pcb + 1);
            u64t mm = pk2(mask, mask);
            zqh[j * 4 + 0] = mul2(qa.x, mm);
            zqh[j * 4 + 1] = mul2(qa.y, mm);
            zqh[j * 4 + 2] = mul2(qb.x, mm);
            zqh[j * 4 + 3] = mul2(qb.y, mm);

            if (wq == 0) {
#pragma unroll
                for (int p = 0; p < 4; p++) {
                    float2 u = upk2(zqh[j * 4 + p]);
                    g_ZQ[(size_t)(nq * 8 + 2 * p) * NCOL + col] = u.x;
                    g_ZQ[(size_t)(nq * 8 + 2 * p + 1) * NCOL + col] = u.y;
                }
                if (write_idx)
                    out[QOUT_ELEMS + (size_t)(nq * BB + b) * TT + t] = (float)bki;
            }
            // no second barrier: next step uses the other sArg buffer
        }

        // fold chunk into all future ZE0 rows — zero barriers (sGAll already staged)
        for (int fc = c + 1; fc < 8; fc++) {
#pragma unroll
            for (int r8 = 0; r8 < 8; r8++) {
                int r = wq * 8 + r8;
                const u64t* gp = reinterpret_cast<const u64t*>(&sGAll[(fc * 32 + r) * 32]);
                u64t a = mul2(gp[0], zqh[0]);
#pragma unroll
                for (int q = 1; q < 16; q++) fma2(a, gp[q], zqh[q]);
                float2 u = upk2(a);
                size_t idx = (size_t)(fc * 32 + r) * NCOL + col;
                g_ZE0[idx] -= (u.x + u.y);
            }
        }
    }
}

// ---------------- gemmQ: qout = WoT x ZQ + mask*bsum, k-tile 32, cp.async ----------------
__global__ void __launch_bounds__(256, 2)
gemmQ(float* __restrict__ out, int out_size) {
    extern __shared__ float gsm[];
    float* As = gsm;               // [2][32*64]
    float* Bs = gsm + 2 * 2048;    // [2][32*264]
    if (out_size < QOUT_ELEMS) return;
    const int tid  = threadIdx.x;
    const int wm   = tid >> 5;
    const int lane = tid & 31;
    const int bm  = blockIdx.x * 64;       // d-tile
    const int cb0 = blockIdx.y * 256;
    const int b   = cb0 >> 12, t0 = cb0 & 4095;
    const int len = g_len[b];

    u64t acc[8][4];
#pragma unroll
    for (int i = 0; i < 8; i++)
#pragma unroll
        for (int p = 0; p < 4; p++) acc[i][p] = 0ull;

    {
#pragma unroll
        for (int it = 0; it < 2; it++) {
            int f = it * 256 + tid, row = f >> 4, c4 = f & 15;
            cpa16(s2u(&As[row * 64 + c4 * 4]),
                  &g_WoT2[(size_t)row * DD + bm + c4 * 4]);
        }
#pragma unroll
        for (int it = 0; it < 8; it++) {
            int f = it * 256 + tid, brow = f >> 6, bc4 = f & 63;
            cpa16(s2u(&Bs[brow * 264 + bc4 * 4]),
                  g_ZQ + (size_t)brow * NCOL + cb0 + bc4 * 4);
        }
        cpa_commit();
    }

    int buf = 0;
    for (int kk = 0; kk < 256; kk += 32) {
        cpa_wait_all();
        __syncthreads();
        if (kk + 32 < 256) {
            int nb = buf ^ 1;
#pragma unroll
            for (int it = 0; it < 2; it++) {
                int f = it * 256 + tid, row = f >> 4, c4 = f & 15;
                cpa16(s2u(&As[nb * 2048 + row * 64 + c4 * 4]),
                      &g_WoT2[(size_t)(kk + 32 + row) * DD + bm + c4 * 4]);
            }
#pragma unroll
            for (int it = 0; it < 8; it++) {
                int f = it * 256 + tid, brow = f >> 6, bc4 = f & 63;
                cpa16(s2u(&Bs[nb * 8448 + brow * 264 + bc4 * 4]),
                      g_ZQ + (size_t)(kk + 32 + brow) * NCOL + cb0 + bc4 * 4);
            }
            cpa_commit();
        }
        const float* Ab = As + buf * 2048;
        const float* Bb = Bs + buf * 8448;
#pragma unroll
        for (int k = 0; k < 32; k++) {
            const float* ar = &Ab[k * 64 + wm * 8];
            float4 a0 = *reinterpret_cast<const float4*>(ar);
            float4 a1 = *reinterpret_cast<const float4*>(ar + 4);
            ulonglong2 bA = *reinterpret_cast<const ulonglong2*>(&Bb[k * 264 + lane * 4]);
            ulonglong2 bB = *reinterpret_cast<const ulonglong2*>(&Bb[k * 264 + 128 + lane * 4]);
            float aa[8] = {a0.x, a0.y, a0.z, a0.w, a1.x, a1.y, a1.z, a1.w};
#pragma unroll
            for (int i = 0; i < 8; i++) {
                u64t ap = pk2(aa[i], aa[i]);
                fma2(acc[i][0], ap, bA.x); fma2(acc[i][1], ap, bA.y);
                fma2(acc[i][2], ap, bB.x); fma2(acc[i][3], ap, bB.y);
            }
        }
        buf ^= 1;
    }
    {
        int tA = t0 + lane * 4, tB = tA + 128;
        float mA0 = (tA     < len) ? 1.0f : 0.0f;
        float mA1 = (tA + 1 < len) ? 1.0f : 0.0f;
        float mA2 = (tA + 2 < len) ? 1.0f : 0.0f;
        float mA3 = (tA + 3 < len) ? 1.0f : 0.0f;
        float mB0 = (tB     < len) ? 1.0f : 0.0f;
        float mB1 = (tB + 1 < len) ? 1.0f : 0.0f;
        float mB2 = (tB + 2 < len) ? 1.0f : 0.0f;
        float mB3 = (tB + 3 < len) ? 1.0f : 0.0f;
#pragma unroll
        for (int i = 0; i < 8; i++) {
            int d = bm + wm * 8 + i;
            float bs = __ldg(g_bsum + d);
            float* dst = out + (size_t)b * DD * TT + (size_t)d * TT + t0 + lane * 4;
            float2 u0 = upk2(acc[i][0]), u1 = upk2(acc[i][1]);
            float2 u2 = upk2(acc[i][2]), u3 = upk2(acc[i][3]);
            float4 oA, oB;
            oA.x = (u0.x + mA0 * bs) * mA0;
            oA.y = (u0.y + mA1 * bs) * mA1;
            oA.z = (u1.x + mA2 * bs) * mA2;
            oA.w = (u1.y + mA3 * bs) * mA3;
            oB.x = (u2.x + mB0 * bs) * mB0;
            oB.y = (u2.y + mB1 * bs) * mB1;
            oB.z = (u3.x + mB2 * bs) * mB2;
            oB.w = (u3.y + mB3 * bs) * mB3;
            *reinterpret_cast<float4*>(dst)       = oA;
            *reinterpret_cast<float4*>(dst + 128) = oB;
        }
    }
}

// ---------------------------------------------------------------------------
extern "C" void kernel_launch(void* const* d_in, const int* in_sizes, int n_in,
                              void* d_out, int out_size) {
    const float*     z     = (const float*)d_in[0];
    const long long* len   = (const long long*)d_in[1];
    const float*     W_in  = (const float*)d_in[2];
    const float*     b_in  = (const float*)d_in[3];
    const float*     W_out = (const float*)d_in[4];
    const float*     b_out = (const float*)d_in[5];
    const float*     cbk   = (const float*)d_in[6];
    float* out = (float*)d_out;

    cudaFuncSetAttribute(rvq_scan,
                         cudaFuncAttributeMaxDynamicSharedMemorySize, SCAN_SMEM_BYTES);
    cudaFuncSetAttribute(gemmZE,
                         cudaFuncAttributeMaxDynamicSharedMemorySize, GEMM_SMEM_BYTES);
    cudaFuncSetAttribute(gemmQ,
                         cudaFuncAttributeMaxDynamicSharedMemorySize, GEMM_SMEM_BYTES);

    kPre<<<1024, 256>>>(W_in, b_in, W_out, b_out, cbk, len, out, out_size);
    kWbo<<<1024, 256>>>(W_in, b_out);
    kG<<<dim3(4, 4), 256>>>();
    gemmZE<<<dim3(4, 128), 256, GEMM_SMEM_BYTES>>>(z);
    rvq_scan<<<512, 256, SCAN_SMEM_BYTES>>>(b_in, cbk, out, out_size);
    gemmQ<<<dim3(16, 128), 256, GEMM_SMEM_BYTES>>>(out, out_size);
}